// round 1
// baseline (speedup 1.0000x reference)
#include <cuda_runtime.h>
#include <cuda_bf16.h>
#include <cstdint>

// Problem constants
#define NN 50000
#define EE 1000000
#define F_IN 256
#define UNITS 128
#define NCLS 40
#define NCLS_PAD 64
#define EPSBN 1e-3f

// ---------------- scratch (static device globals; no allocation) ----------------
__device__ __align__(16) float g_deg[NN];              // deg, then dinv in-place
__device__ __align__(16) float g_norm[EE];             // per-edge normalized weight
__device__ __align__(16) float g_hw[(size_t)NN * 128]; // h @ w_gcn
__device__ __align__(16) float g_acc[(size_t)NN * 128];// self-path + aggregated messages
__device__ __align__(16) float g_h[(size_t)NN * 128];  // layer activation
__device__ __align__(16) float g_w3p[128 * NCLS_PAD * 2 + NCLS_PAD]; // padded wg3, ws3, b3

// ---------------- helpers ----------------
__device__ __forceinline__ void red_add_v4(float4* addr, float a, float b, float c, float d) {
    asm volatile("red.global.add.v4.f32 [%0], {%1, %2, %3, %4};"
                 :: "l"(addr), "f"(a), "f"(b), "f"(c), "f"(d) : "memory");
}

// ---------------- small kernels ----------------
__global__ void zero_kernel(float* p, int n) {
    int i = blockIdx.x * blockDim.x + threadIdx.x;
    if (i < n) p[i] = 0.f;
}

__global__ void scatter_deg_kernel(const int* __restrict__ dst, const float* __restrict__ w, int e) {
    int i = blockIdx.x * blockDim.x + threadIdx.x;
    if (i < e) atomicAdd(&g_deg[dst[i]], w[i]);
}

__global__ void dinv_kernel(int n) {
    int i = blockIdx.x * blockDim.x + threadIdx.x;
    if (i < n) {
        float d = g_deg[i];
        g_deg[i] = (d > 0.f) ? rsqrtf(d) : 0.f;
    }
}

__global__ void normw_kernel(const int* __restrict__ src, const int* __restrict__ dst,
                             const float* __restrict__ w, int e) {
    int i = blockIdx.x * blockDim.x + threadIdx.x;
    if (i < e) g_norm[i] = g_deg[src[i]] * w[i] * g_deg[dst[i]];
}

// pad layer-3 weights [128,40] -> [128,64] (zeros in cols 40..63), bias too
__global__ void pad_w3_kernel(const float* __restrict__ wg, const float* __restrict__ ws,
                              const float* __restrict__ b) {
    int i = blockIdx.x * blockDim.x + threadIdx.x;
    if (i < 128 * NCLS_PAD) {
        int r = i / NCLS_PAD, c = i % NCLS_PAD;
        float vg = (c < NCLS) ? wg[r * NCLS + c] : 0.f;
        float vs = (c < NCLS) ? ws[r * NCLS + c] : 0.f;
        g_w3p[i] = vg;
        g_w3p[128 * NCLS_PAD + i] = vs;
    }
    if (i < NCLS_PAD) g_w3p[2 * 128 * NCLS_PAD + i] = (i < NCLS) ? b[i] : 0.f;
}

// ---------------- tiled fp32 GEMM: out[nrows, F] = H[nrows, K] @ W[K, F] (+bias) ----------------
template<int K, int F, bool BIAS>
__global__ void __launch_bounds__(256) gemm_kernel(const float* __restrict__ H,
                                                   const float* __restrict__ W,
                                                   const float* __restrict__ bias,
                                                   float* __restrict__ out, int nrows) {
    constexpr int TN = 4;
    constexpr int TM = 8;
    constexpr int CG = F / TN;      // col groups: 32 (F=128) or 16 (F=64)
    constexpr int RG = 256 / CG;    // row groups: 8 or 16
    constexpr int BM = RG * TM;     // 64 or 128
    constexpr int BK = 32;

    __shared__ float Hs[BK][BM + 1];   // transposed tile, padded vs bank conflicts
    __shared__ float Ws[BK][F];

    const int tid = threadIdx.x;
    const int tc = tid % CG;
    const int tr = tid / CG;
    const int row0 = blockIdx.x * BM;

    float acc[TM][TN];
#pragma unroll
    for (int i = 0; i < TM; i++)
#pragma unroll
        for (int j = 0; j < TN; j++) acc[i][j] = 0.f;

    for (int kt = 0; kt < K; kt += BK) {
#pragma unroll
        for (int i = 0; i < (BM * BK) / 256; i++) {
            int idx = tid + i * 256;
            int m = idx / BK, k = idx % BK;
            int gr = row0 + m;
            Hs[k][m] = (gr < nrows) ? H[(size_t)gr * K + kt + k] : 0.f;
        }
#pragma unroll
        for (int i = 0; i < (BK * F) / 256; i++) {
            int idx = tid + i * 256;
            int k = idx / F, f = idx % F;
            Ws[k][f] = W[(size_t)(kt + k) * F + f];
        }
        __syncthreads();
#pragma unroll
        for (int k = 0; k < BK; k++) {
            float wv[TN];
#pragma unroll
            for (int j = 0; j < TN; j++) wv[j] = Ws[k][tc * TN + j];
#pragma unroll
            for (int i = 0; i < TM; i++) {
                float hv = Hs[k][tr * TM + i];
#pragma unroll
                for (int j = 0; j < TN; j++) acc[i][j] = fmaf(hv, wv[j], acc[i][j]);
            }
        }
        __syncthreads();
    }

#pragma unroll
    for (int i = 0; i < TM; i++) {
        int gr = row0 + tr * TM + i;
        if (gr < nrows) {
            float4 v;
            float* a = acc[i];
            if (BIAS) {
                v.x = a[0] + bias[tc * TN + 0];
                v.y = a[1] + bias[tc * TN + 1];
                v.z = a[2] + bias[tc * TN + 2];
                v.w = a[3] + bias[tc * TN + 3];
            } else {
                v.x = a[0]; v.y = a[1]; v.z = a[2]; v.w = a[3];
            }
            *reinterpret_cast<float4*>(&out[(size_t)gr * F + tc * TN]) = v;
        }
    }
}

// ---------------- edge gather/scatter: one warp per edge, F=128 ----------------
__global__ void edge_scatter128_kernel(const int* __restrict__ src, const int* __restrict__ dst, int e) {
    int t = blockIdx.x * blockDim.x + threadIdx.x;
    int eid = t >> 5;
    int c = t & 31;
    if (eid >= e) return;
    int s = src[eid];
    int d = dst[eid];
    float nw = g_norm[eid];
    const float4* row = reinterpret_cast<const float4*>(g_hw + (size_t)s * 128);
    float4 v = __ldg(&row[c]);
    float4* orow = reinterpret_cast<float4*>(g_acc + (size_t)d * 128);
    red_add_v4(&orow[c], v.x * nw, v.y * nw, v.z * nw, v.w * nw);
}

// layer 3: padded width 64, 40 useful -> 10 float4 chunks/edge
__global__ void edge_scatter40_kernel(const int* __restrict__ src, const int* __restrict__ dst, int e) {
    int t = blockIdx.x * blockDim.x + threadIdx.x;
    int eid = t / 10;
    int c = t - eid * 10;
    if (eid >= e) return;
    int s = src[eid];
    int d = dst[eid];
    float nw = g_norm[eid];
    float4 v = __ldg(reinterpret_cast<const float4*>(g_hw + (size_t)s * NCLS_PAD + c * 4));
    red_add_v4(reinterpret_cast<float4*>(g_acc + (size_t)d * NCLS_PAD + c * 4),
               v.x * nw, v.y * nw, v.z * nw, v.w * nw);
}

// ---------------- batchnorm (+relu) ----------------
__global__ void bn_relu128_kernel(const float* __restrict__ in,
                                  const float* __restrict__ gamma, const float* __restrict__ beta,
                                  const float* __restrict__ mean, const float* __restrict__ var,
                                  float* __restrict__ out, int total) {
    int i = blockIdx.x * blockDim.x + threadIdx.x;
    if (i >= total) return;
    int c = i & 127;
    float v = in[i];
    v = (v - mean[c]) * rsqrtf(var[c] + EPSBN) * gamma[c] + beta[c];
    out[i] = fmaxf(v, 0.f);
}

// layer 3: read stride 64, write stride 40, no relu
__global__ void bn3_kernel(const float* __restrict__ in,
                           const float* __restrict__ gamma, const float* __restrict__ beta,
                           const float* __restrict__ mean, const float* __restrict__ var,
                           float* __restrict__ out, int total) {
    int i = blockIdx.x * blockDim.x + threadIdx.x;
    if (i >= total) return;
    int r = i / NCLS;
    int c = i - r * NCLS;
    float v = in[(size_t)r * NCLS_PAD + c];
    out[i] = (v - mean[c]) * rsqrtf(var[c] + EPSBN) * gamma[c] + beta[c];
}

// ---------------- launch ----------------
extern "C" void kernel_launch(void* const* d_in, const int* in_sizes, int n_in,
                              void* d_out, int out_size) {
    const float* x   = (const float*)d_in[0];
    const int*   ei  = (const int*)d_in[1];
    const float* ew  = (const float*)d_in[2];
    const int* src = ei;
    const int* dst = ei + EE;

    const float* wg1 = (const float*)d_in[3];
    const float* ws1 = (const float*)d_in[4];
    const float* b1  = (const float*)d_in[5];
    const float* gm1 = (const float*)d_in[6];
    const float* bt1 = (const float*)d_in[7];
    const float* mn1 = (const float*)d_in[8];
    const float* vr1 = (const float*)d_in[9];

    const float* wg2 = (const float*)d_in[10];
    const float* ws2 = (const float*)d_in[11];
    const float* b2  = (const float*)d_in[12];
    const float* gm2 = (const float*)d_in[13];
    const float* bt2 = (const float*)d_in[14];
    const float* mn2 = (const float*)d_in[15];
    const float* vr2 = (const float*)d_in[16];

    const float* wg3 = (const float*)d_in[17];
    const float* ws3 = (const float*)d_in[18];
    const float* b3  = (const float*)d_in[19];
    const float* gm3 = (const float*)d_in[20];
    const float* bt3 = (const float*)d_in[21];
    const float* mn3 = (const float*)d_in[22];
    const float* vr3 = (const float*)d_in[23];

    float* out = (float*)d_out;

    // device scratch addresses (symbol query: capture-safe, no allocation)
    float *p_deg, *p_hw, *p_acc, *p_h, *p_w3p;
    cudaGetSymbolAddress((void**)&p_deg, g_deg);
    cudaGetSymbolAddress((void**)&p_hw,  g_hw);
    cudaGetSymbolAddress((void**)&p_acc, g_acc);
    cudaGetSymbolAddress((void**)&p_h,   g_h);
    cudaGetSymbolAddress((void**)&p_w3p, g_w3p);

    const int TPB = 256;
    // ---- degree / normalization ----
    zero_kernel<<<(NN + TPB - 1) / TPB, TPB>>>(p_deg, NN);
    scatter_deg_kernel<<<(EE + TPB - 1) / TPB, TPB>>>(dst, ew, EE);
    dinv_kernel<<<(NN + TPB - 1) / TPB, TPB>>>(NN);
    normw_kernel<<<(EE + TPB - 1) / TPB, TPB>>>(src, dst, ew, EE);

    // ---- layer 1: K=256, F=128 ----
    {
        const int BM = 64;
        int grid = (NN + BM - 1) / BM;
        gemm_kernel<F_IN, 128, false><<<grid, 256>>>(x, wg1, nullptr, p_hw, NN);
        gemm_kernel<F_IN, 128, true ><<<grid, 256>>>(x, ws1, b1, p_acc, NN);
    }
    edge_scatter128_kernel<<<(int)(((long long)EE * 32 + TPB - 1) / TPB), TPB>>>(src, dst, EE);
    bn_relu128_kernel<<<(NN * 128 + TPB - 1) / TPB, TPB>>>(p_acc, gm1, bt1, mn1, vr1, p_h, NN * 128);

    // ---- layer 2: K=128, F=128 ----
    {
        const int BM = 64;
        int grid = (NN + BM - 1) / BM;
        gemm_kernel<UNITS, 128, false><<<grid, 256>>>(p_h, wg2, nullptr, p_hw, NN);
        gemm_kernel<UNITS, 128, true ><<<grid, 256>>>(p_h, ws2, b2, p_acc, NN);
    }
    edge_scatter128_kernel<<<(int)(((long long)EE * 32 + TPB - 1) / TPB), TPB>>>(src, dst, EE);
    bn_relu128_kernel<<<(NN * 128 + TPB - 1) / TPB, TPB>>>(p_acc, gm2, bt2, mn2, vr2, p_h, NN * 128);

    // ---- layer 3: K=128, F=40 (padded to 64) ----
    pad_w3_kernel<<<(128 * NCLS_PAD + TPB - 1) / TPB, TPB>>>(wg3, ws3, b3);
    {
        const int BM = 128;
        int grid = (NN + BM - 1) / BM;
        gemm_kernel<UNITS, NCLS_PAD, false><<<grid, 256>>>(p_h, p_w3p, nullptr, p_hw, NN);
        gemm_kernel<UNITS, NCLS_PAD, true ><<<grid, 256>>>(p_h, p_w3p + 128 * NCLS_PAD,
                                                           p_w3p + 2 * 128 * NCLS_PAD, p_acc, NN);
    }
    edge_scatter40_kernel<<<(int)(((long long)EE * 10 + TPB - 1) / TPB), TPB>>>(src, dst, EE);
    bn3_kernel<<<(NN * NCLS + TPB - 1) / TPB, TPB>>>(p_acc, gm3, bt3, mn3, vr3, out, NN * NCLS);
}

// round 3
// speedup vs baseline: 1.2541x; 1.2541x over previous
#include <cuda_runtime.h>
#include <cuda_bf16.h>
#include <cstdint>

// Problem constants
#define NN 50000
#define EE 1000000
#define F_IN 256
#define UNITS 128
#define NCLS 40
#define NCLS_PAD 64
#define EPSBN 1e-3f

// ================= mma.sync helpers (sm_80+ baseline PTX; works on plain sm_103) ====
__device__ __forceinline__ uint32_t smem_to_u32(const void* p) {
    uint32_t a;
    asm("{ .reg .u64 t; cvta.to.shared.u64 t, %1; cvt.u32.u64 %0, t; }" : "=r"(a) : "l"(p));
    return a;
}
#define LDSM_X4(r, addr) \
    asm volatile("ldmatrix.sync.aligned.m8n8.x4.shared.b16 {%0,%1,%2,%3}, [%4];" \
        : "=r"((r)[0]), "=r"((r)[1]), "=r"((r)[2]), "=r"((r)[3]) : "r"(addr))
#define LDSM_X2(r, addr) \
    asm volatile("ldmatrix.sync.aligned.m8n8.x2.shared.b16 {%0,%1}, [%2];" \
        : "=r"((r)[0]), "=r"((r)[1]) : "r"(addr))

__device__ __forceinline__ void mma_bf16(float* c, const uint32_t* a, const uint32_t* b) {
    asm volatile("mma.sync.aligned.m16n8k16.row.col.f32.bf16.bf16.f32 "
        "{%0,%1,%2,%3}, {%4,%5,%6,%7}, {%8,%9}, {%0,%1,%2,%3};"
        : "+f"(c[0]), "+f"(c[1]), "+f"(c[2]), "+f"(c[3])
        : "r"(a[0]), "r"(a[1]), "r"(a[2]), "r"(a[3]), "r"(b[0]), "r"(b[1]));
}

// ================= scratch (static device globals) =================
__device__ __align__(16) float g_deg[NN];
__device__ __align__(16) float g_norm[EE];
__device__ __align__(16) float g_hw[(size_t)NN * 128];
__device__ __align__(16) float g_acc[(size_t)NN * 128];
__device__ __align__(16) __nv_bfloat16 g_xhi[(size_t)NN * F_IN];
__device__ __align__(16) __nv_bfloat16 g_xlo[(size_t)NN * F_IN];
__device__ __align__(16) __nv_bfloat16 g_hhi[(size_t)NN * 128];
__device__ __align__(16) __nv_bfloat16 g_hlo[(size_t)NN * 128];
__device__ __align__(16) __nv_bfloat16 g_w1hi[256 * 256];
__device__ __align__(16) __nv_bfloat16 g_w1lo[256 * 256];
__device__ __align__(16) __nv_bfloat16 g_w2hi[256 * 128];
__device__ __align__(16) __nv_bfloat16 g_w2lo[256 * 128];
__device__ __align__(16) __nv_bfloat16 g_w3hi[128 * 128];
__device__ __align__(16) __nv_bfloat16 g_w3lo[128 * 128];
__device__ __align__(16) float g_b3p[NCLS_PAD];

// ================= small kernels =================
__global__ void zero_kernel(float* p, int n) {
    int i = blockIdx.x * blockDim.x + threadIdx.x;
    if (i < n) p[i] = 0.f;
}
__global__ void scatter_deg_kernel(const int* __restrict__ dst, const float* __restrict__ w, int e) {
    int i = blockIdx.x * blockDim.x + threadIdx.x;
    if (i < e) atomicAdd(&g_deg[dst[i]], w[i]);
}
__global__ void dinv_kernel(int n) {
    int i = blockIdx.x * blockDim.x + threadIdx.x;
    if (i < n) {
        float d = g_deg[i];
        g_deg[i] = (d > 0.f) ? rsqrtf(d) : 0.f;
    }
}
__global__ void normw_kernel(const int* __restrict__ src, const int* __restrict__ dst,
                             const float* __restrict__ w, int e) {
    int i = blockIdx.x * blockDim.x + threadIdx.x;
    if (i < e) g_norm[i] = g_deg[src[i]] * w[i] * g_deg[dst[i]];
}

// weight prep: Wcat row n in [0, 2*NHALF): n<NHALF -> Wg^T (padded), else Ws^T (padded)
__global__ void prep_w_kernel(const float* __restrict__ Wg, const float* __restrict__ Ws,
                              int K, int NV, int NHALF,
                              __nv_bfloat16* __restrict__ hi, __nv_bfloat16* __restrict__ lo) {
    int idx = blockIdx.x * blockDim.x + threadIdx.x;
    int total = 2 * NHALF * K;
    if (idx >= total) return;
    int n = idx / K, k = idx - n * K;
    float v = 0.f;
    if (n < NHALF) { if (n < NV) v = Wg[k * NV + n]; }
    else { int c = n - NHALF; if (c < NV) v = Ws[k * NV + c]; }
    __nv_bfloat16 h = __float2bfloat16(v);
    hi[idx] = h;
    lo[idx] = __float2bfloat16(v - __bfloat162float(h));
}
__global__ void prep_b3_kernel(const float* __restrict__ b) {
    int i = threadIdx.x;
    if (i < NCLS_PAD) g_b3p[i] = (i < NCLS) ? b[i] : 0.f;
}
__global__ void split_kernel(const float* __restrict__ in,
                             __nv_bfloat16* __restrict__ hi, __nv_bfloat16* __restrict__ lo, int n) {
    int i = blockIdx.x * blockDim.x + threadIdx.x;
    if (i >= n) return;
    float v = in[i];
    __nv_bfloat16 h = __float2bfloat16(v);
    hi[i] = h;
    lo[i] = __float2bfloat16(v - __bfloat162float(h));
}

// ================= mma.sync bf16-split GEMM =================
// Wcat: [2*NHALF, K] bf16 hi/lo (row n = output column n).
// grid: (ceil(nrows/128), 2*NHALF/128). CTA computes out[:, n0:n0+128].
// Columns < NHALF -> out_gcn; >= NHALF -> out_self (+bias).
template<int K, int NHALF>
__global__ void __launch_bounds__(256, 1) gcn_gemm_mma(
    const __nv_bfloat16* __restrict__ Ahi, const __nv_bfloat16* __restrict__ Alo,
    const __nv_bfloat16* __restrict__ Whi, const __nv_bfloat16* __restrict__ Wlo,
    const float* __restrict__ bias,
    float* __restrict__ out_gcn, float* __restrict__ out_self, int nrows)
{
    constexpr int BK = 32;           // bf16 per k-chunk
    constexpr int NIT = K / BK;
    constexpr int ROWB = 80;         // smem bytes per 32-bf16 row (conflict-free stride)
    constexpr int TILE = 128 * ROWB; // 10240 bytes

    __shared__ __align__(16) unsigned char sm[4 * TILE];  // Ahi | Alo | Bhi | Blo

    const int tid = threadIdx.x;
    const int lane = tid & 31;
    const int wid = tid >> 5;
    const int row0 = blockIdx.x * 128;
    const int n0 = blockIdx.y * 128;
    const uint32_t sbase = smem_to_u32(sm);

    const int wm = wid >> 2;          // 0..1
    const int wn = wid & 3;           // 0..3
    const int m0w = wm * 64;
    const int n0w = wn * 32;

    float acc[4][4][4];
#pragma unroll
    for (int mt = 0; mt < 4; mt++)
#pragma unroll
        for (int nt = 0; nt < 4; nt++)
#pragma unroll
            for (int j = 0; j < 4; j++) acc[mt][nt][j] = 0.f;

    for (int kc = 0; kc < NIT; kc++) {
        // ---- load k-slab into smem: A(128x32) hi/lo, B(128x32) hi/lo ----
#pragma unroll
        for (int t = 0; t < 2; t++) {
            int i = tid + t * 256;
            int r = i >> 2, q = i & 3;
            size_t gcol = (size_t)kc * BK + q * 8;
            uint32_t soff = r * ROWB + q * 16;
            // A
            uint4 vh = make_uint4(0, 0, 0, 0), vl = make_uint4(0, 0, 0, 0);
            int grow = row0 + r;
            if (grow < nrows) {
                vh = *reinterpret_cast<const uint4*>(Ahi + (size_t)grow * K + gcol);
                vl = *reinterpret_cast<const uint4*>(Alo + (size_t)grow * K + gcol);
            }
            *reinterpret_cast<uint4*>(sm + soff)        = vh;
            *reinterpret_cast<uint4*>(sm + TILE + soff) = vl;
            // B
            int brow = n0 + r;
            uint4 wh = *reinterpret_cast<const uint4*>(Whi + (size_t)brow * K + gcol);
            uint4 wl = *reinterpret_cast<const uint4*>(Wlo + (size_t)brow * K + gcol);
            *reinterpret_cast<uint4*>(sm + 2 * TILE + soff) = wh;
            *reinterpret_cast<uint4*>(sm + 3 * TILE + soff) = wl;
        }
        __syncthreads();

#pragma unroll
        for (int ks = 0; ks < 2; ks++) {
            uint32_t ah[4][4], al[4][4], bh[4][2], bl[4][2];
#pragma unroll
            for (int mt = 0; mt < 4; mt++) {
                uint32_t addr = sbase +
                    (uint32_t)((m0w + mt * 16 + (lane & 15)) * ROWB + (ks * 2 + (lane >> 4)) * 16);
                LDSM_X4(ah[mt], addr);
                LDSM_X4(al[mt], addr + TILE);
            }
#pragma unroll
            for (int nt = 0; nt < 4; nt++) {
                uint32_t addr = sbase + 2 * TILE +
                    (uint32_t)((n0w + nt * 8 + (lane & 7)) * ROWB + (ks * 2 + ((lane >> 3) & 1)) * 16);
                LDSM_X2(bh[nt], addr);
                LDSM_X2(bl[nt], addr + TILE);
            }
#pragma unroll
            for (int mt = 0; mt < 4; mt++)
#pragma unroll
                for (int nt = 0; nt < 4; nt++) {
                    mma_bf16(acc[mt][nt], ah[mt], bh[nt]);
                    mma_bf16(acc[mt][nt], ah[mt], bl[nt]);
                    mma_bf16(acc[mt][nt], al[mt], bh[nt]);
                }
        }
        __syncthreads();
    }

    // ---- epilogue: fragment -> global fp32 ----
#pragma unroll
    for (int mt = 0; mt < 4; mt++) {
        int rlo = row0 + m0w + mt * 16 + (lane >> 2);
        int rhi = rlo + 8;
#pragma unroll
        for (int nt = 0; nt < 4; nt++) {
            int gn = n0 + n0w + nt * 8 + (lane & 3) * 2;
            bool isg = gn < NHALF;
            int col = isg ? gn : gn - NHALF;
            float bx = 0.f, by = 0.f;
            float* base = isg ? out_gcn : out_self;
            if (!isg) { bx = __ldg(&bias[col]); by = __ldg(&bias[col + 1]); }
            if (rlo < nrows) {
                float2 v = make_float2(acc[mt][nt][0] + bx, acc[mt][nt][1] + by);
                *reinterpret_cast<float2*>(base + (size_t)rlo * NHALF + col) = v;
            }
            if (rhi < nrows) {
                float2 v = make_float2(acc[mt][nt][2] + bx, acc[mt][nt][3] + by);
                *reinterpret_cast<float2*>(base + (size_t)rhi * NHALF + col) = v;
            }
        }
    }
}

// ================= edge gather/scatter =================
__device__ __forceinline__ void red_add_v4(float4* addr, float a, float b, float c, float d) {
    asm volatile("red.global.add.v4.f32 [%0], {%1, %2, %3, %4};"
                 :: "l"(addr), "f"(a), "f"(b), "f"(c), "f"(d) : "memory");
}
__global__ void edge_scatter128_kernel(const int* __restrict__ src, const int* __restrict__ dst, int e) {
    int t = blockIdx.x * blockDim.x + threadIdx.x;
    int eid = t >> 5;
    int c = t & 31;
    if (eid >= e) return;
    int s = src[eid];
    int d = dst[eid];
    float nw = g_norm[eid];
    const float4* row = reinterpret_cast<const float4*>(g_hw + (size_t)s * 128);
    float4 v = __ldg(&row[c]);
    float4* orow = reinterpret_cast<float4*>(g_acc + (size_t)d * 128);
    red_add_v4(&orow[c], v.x * nw, v.y * nw, v.z * nw, v.w * nw);
}
__global__ void edge_scatter40_kernel(const int* __restrict__ src, const int* __restrict__ dst, int e) {
    int t = blockIdx.x * blockDim.x + threadIdx.x;
    int eid = t / 10;
    int c = t - eid * 10;
    if (eid >= e) return;
    int s = src[eid];
    int d = dst[eid];
    float nw = g_norm[eid];
    float4 v = __ldg(reinterpret_cast<const float4*>(g_hw + (size_t)s * NCLS_PAD + c * 4));
    red_add_v4(reinterpret_cast<float4*>(g_acc + (size_t)d * NCLS_PAD + c * 4),
               v.x * nw, v.y * nw, v.z * nw, v.w * nw);
}

// ================= batchnorm =================
__global__ void bn_relu_split_kernel(const float* __restrict__ in,
                                     const float* __restrict__ gamma, const float* __restrict__ beta,
                                     const float* __restrict__ mean, const float* __restrict__ var,
                                     __nv_bfloat16* __restrict__ hi, __nv_bfloat16* __restrict__ lo,
                                     int total) {
    int i = blockIdx.x * blockDim.x + threadIdx.x;
    if (i >= total) return;
    int c = i & 127;
    float v = in[i];
    v = (v - mean[c]) * rsqrtf(var[c] + EPSBN) * gamma[c] + beta[c];
    v = fmaxf(v, 0.f);
    __nv_bfloat16 h = __float2bfloat16(v);
    hi[i] = h;
    lo[i] = __float2bfloat16(v - __bfloat162float(h));
}
__global__ void bn3_kernel(const float* __restrict__ in,
                           const float* __restrict__ gamma, const float* __restrict__ beta,
                           const float* __restrict__ mean, const float* __restrict__ var,
                           float* __restrict__ out, int total) {
    int i = blockIdx.x * blockDim.x + threadIdx.x;
    if (i >= total) return;
    int r = i / NCLS;
    int c = i - r * NCLS;
    float v = in[(size_t)r * NCLS_PAD + c];
    out[i] = (v - mean[c]) * rsqrtf(var[c] + EPSBN) * gamma[c] + beta[c];
}

// ================= launch =================
extern "C" void kernel_launch(void* const* d_in, const int* in_sizes, int n_in,
                              void* d_out, int out_size) {
    const float* x   = (const float*)d_in[0];
    const int*   ei  = (const int*)d_in[1];
    const float* ew  = (const float*)d_in[2];
    const int* src = ei;
    const int* dst = ei + EE;

    const float* wg1 = (const float*)d_in[3];
    const float* ws1 = (const float*)d_in[4];
    const float* b1  = (const float*)d_in[5];
    const float* gm1 = (const float*)d_in[6];
    const float* bt1 = (const float*)d_in[7];
    const float* mn1 = (const float*)d_in[8];
    const float* vr1 = (const float*)d_in[9];

    const float* wg2 = (const float*)d_in[10];
    const float* ws2 = (const float*)d_in[11];
    const float* b2  = (const float*)d_in[12];
    const float* gm2 = (const float*)d_in[13];
    const float* bt2 = (const float*)d_in[14];
    const float* mn2 = (const float*)d_in[15];
    const float* vr2 = (const float*)d_in[16];

    const float* wg3 = (const float*)d_in[17];
    const float* ws3 = (const float*)d_in[18];
    const float* b3  = (const float*)d_in[19];
    const float* gm3 = (const float*)d_in[20];
    const float* bt3 = (const float*)d_in[21];
    const float* mn3 = (const float*)d_in[22];
    const float* vr3 = (const float*)d_in[23];

    float* out = (float*)d_out;

    float *p_deg, *p_hw, *p_acc, *p_b3p;
    __nv_bfloat16 *p_xhi, *p_xlo, *p_hhi, *p_hlo;
    __nv_bfloat16 *p_w1hi, *p_w1lo, *p_w2hi, *p_w2lo, *p_w3hi, *p_w3lo;
    cudaGetSymbolAddress((void**)&p_deg, g_deg);
    cudaGetSymbolAddress((void**)&p_hw,  g_hw);
    cudaGetSymbolAddress((void**)&p_acc, g_acc);
    cudaGetSymbolAddress((void**)&p_b3p, g_b3p);
    cudaGetSymbolAddress((void**)&p_xhi, g_xhi);
    cudaGetSymbolAddress((void**)&p_xlo, g_xlo);
    cudaGetSymbolAddress((void**)&p_hhi, g_hhi);
    cudaGetSymbolAddress((void**)&p_hlo, g_hlo);
    cudaGetSymbolAddress((void**)&p_w1hi, g_w1hi);
    cudaGetSymbolAddress((void**)&p_w1lo, g_w1lo);
    cudaGetSymbolAddress((void**)&p_w2hi, g_w2hi);
    cudaGetSymbolAddress((void**)&p_w2lo, g_w2lo);
    cudaGetSymbolAddress((void**)&p_w3hi, g_w3hi);
    cudaGetSymbolAddress((void**)&p_w3lo, g_w3lo);

    const int TPB = 256;
    const int GRID_M = (NN + 127) / 128;  // 391

    // ---- degree / normalization ----
    zero_kernel<<<(NN + TPB - 1) / TPB, TPB>>>(p_deg, NN);
    scatter_deg_kernel<<<(EE + TPB - 1) / TPB, TPB>>>(dst, ew, EE);
    dinv_kernel<<<(NN + TPB - 1) / TPB, TPB>>>(NN);
    normw_kernel<<<(EE + TPB - 1) / TPB, TPB>>>(src, dst, ew, EE);

    // ---- prep: transposed bf16 hi/lo weights, x split ----
    prep_w_kernel<<<(2 * 128 * 256 + TPB - 1) / TPB, TPB>>>(wg1, ws1, 256, 128, 128, p_w1hi, p_w1lo);
    prep_w_kernel<<<(2 * 128 * 128 + TPB - 1) / TPB, TPB>>>(wg2, ws2, 128, 128, 128, p_w2hi, p_w2lo);
    prep_w_kernel<<<(2 * 64 * 128 + TPB - 1) / TPB, TPB>>>(wg3, ws3, 128, 40, 64, p_w3hi, p_w3lo);
    prep_b3_kernel<<<1, 64>>>(b3);
    split_kernel<<<(NN * F_IN + TPB - 1) / TPB, TPB>>>(x, p_xhi, p_xlo, NN * F_IN);

    // ---- layer 1: K=256, out 2x128 ----
    gcn_gemm_mma<256, 128><<<dim3(GRID_M, 2), 256>>>(p_xhi, p_xlo, p_w1hi, p_w1lo, b1, p_hw, p_acc, NN);
    edge_scatter128_kernel<<<(int)(((long long)EE * 32 + TPB - 1) / TPB), TPB>>>(src, dst, EE);
    bn_relu_split_kernel<<<(NN * 128 + TPB - 1) / TPB, TPB>>>(p_acc, gm1, bt1, mn1, vr1, p_hhi, p_hlo, NN * 128);

    // ---- layer 2: K=128, out 2x128 ----
    gcn_gemm_mma<128, 128><<<dim3(GRID_M, 2), 256>>>(p_hhi, p_hlo, p_w2hi, p_w2lo, b2, p_hw, p_acc, NN);
    edge_scatter128_kernel<<<(int)(((long long)EE * 32 + TPB - 1) / TPB), TPB>>>(src, dst, EE);
    bn_relu_split_kernel<<<(NN * 128 + TPB - 1) / TPB, TPB>>>(p_acc, gm2, bt2, mn2, vr2, p_hhi, p_hlo, NN * 128);

    // ---- layer 3: K=128, out 2x64 (one CTA column covers both halves) ----
    gcn_gemm_mma<128, 64><<<dim3(GRID_M, 1), 256>>>(p_hhi, p_hlo, p_w3hi, p_w3lo, p_b3p, p_hw, p_acc, NN);
    edge_scatter40_kernel<<<(int)(((long long)EE * 10 + TPB - 1) / TPB), TPB>>>(src, dst, EE);
    bn3_kernel<<<(NN * NCLS + TPB - 1) / TPB, TPB>>>(p_acc, gm3, bt3, mn3, vr3, out, NN * NCLS);
}

// round 4
// speedup vs baseline: 1.4830x; 1.1825x over previous
#include <cuda_runtime.h>
#include <cuda_bf16.h>
#include <cstdint>

// Problem constants
#define NN 50000
#define EE 1000000
#define F_IN 256
#define UNITS 128
#define NCLS 40
#define NCLS_PAD 64
#define EPSBN 1e-3f

// ================= mma.sync helpers =================
__device__ __forceinline__ uint32_t smem_to_u32(const void* p) {
    uint32_t a;
    asm("{ .reg .u64 t; cvta.to.shared.u64 t, %1; cvt.u32.u64 %0, t; }" : "=r"(a) : "l"(p));
    return a;
}
#define LDSM_X4(r, addr) \
    asm volatile("ldmatrix.sync.aligned.m8n8.x4.shared.b16 {%0,%1,%2,%3}, [%4];" \
        : "=r"((r)[0]), "=r"((r)[1]), "=r"((r)[2]), "=r"((r)[3]) : "r"(addr))
#define LDSM_X2(r, addr) \
    asm volatile("ldmatrix.sync.aligned.m8n8.x2.shared.b16 {%0,%1}, [%2];" \
        : "=r"((r)[0]), "=r"((r)[1]) : "r"(addr))

__device__ __forceinline__ void mma_bf16(float* c, const uint32_t* a, const uint32_t* b) {
    asm volatile("mma.sync.aligned.m16n8k16.row.col.f32.bf16.bf16.f32 "
        "{%0,%1,%2,%3}, {%4,%5,%6,%7}, {%8,%9}, {%0,%1,%2,%3};"
        : "+f"(c[0]), "+f"(c[1]), "+f"(c[2]), "+f"(c[3])
        : "r"(a[0]), "r"(a[1]), "r"(a[2]), "r"(a[3]), "r"(b[0]), "r"(b[1]));
}

// ================= scratch (static device globals) =================
__device__ __align__(16) float g_deg[NN];             // deg -> dinv in place
__device__ __align__(16) int   g_cnt[NN];
__device__ __align__(16) int   g_rowptr[NN + 1];
__device__ __align__(16) int   g_ssrc[EE];
__device__ __align__(16) float g_sw[EE];
__device__ __align__(16) float g_hw[(size_t)NN * 128];
__device__ __align__(16) float g_acc[(size_t)NN * 128];
__device__ __align__(16) __nv_bfloat16 g_xhi[(size_t)NN * F_IN];
__device__ __align__(16) __nv_bfloat16 g_xlo[(size_t)NN * F_IN];
__device__ __align__(16) __nv_bfloat16 g_hhi[(size_t)NN * 128];
__device__ __align__(16) __nv_bfloat16 g_hlo[(size_t)NN * 128];
__device__ __align__(16) __nv_bfloat16 g_w1hi[256 * 256];
__device__ __align__(16) __nv_bfloat16 g_w1lo[256 * 256];
__device__ __align__(16) __nv_bfloat16 g_w2hi[256 * 128];
__device__ __align__(16) __nv_bfloat16 g_w2lo[256 * 128];
__device__ __align__(16) __nv_bfloat16 g_w3hi[128 * 128];
__device__ __align__(16) __nv_bfloat16 g_w3lo[128 * 128];
__device__ __align__(16) float g_b3p[NCLS_PAD];

// ================= CSR build =================
__global__ void zero_dc_kernel() {
    int i = blockIdx.x * blockDim.x + threadIdx.x;
    if (i < NN) { g_deg[i] = 0.f; g_cnt[i] = 0; }
}
__global__ void count_deg_kernel(const int* __restrict__ dst, const float* __restrict__ w, int e) {
    int i = blockIdx.x * blockDim.x + threadIdx.x;
    if (i < e) {
        int d = dst[i];
        atomicAdd(&g_cnt[d], 1);
        atomicAdd(&g_deg[d], w[i]);
    }
}
__global__ void dinv_kernel(int n) {
    int i = blockIdx.x * blockDim.x + threadIdx.x;
    if (i < n) {
        float d = g_deg[i];
        g_deg[i] = (d > 0.f) ? rsqrtf(d) : 0.f;
    }
}
// one-block scan: cnt -> rowptr (exclusive), zero cnt for fill pass
__global__ void __launch_bounds__(1024) scan_kernel() {
    __shared__ int part[1024];
    const int CH = (NN + 1023) / 1024;
    int t = threadIdx.x;
    int beg = t * CH, end = min(beg + CH, NN);
    int s = 0;
    for (int i = beg; i < end; i++) s += g_cnt[i];
    part[t] = s;
    __syncthreads();
    for (int off = 1; off < 1024; off <<= 1) {
        int v = (t >= off) ? part[t - off] : 0;
        __syncthreads();
        part[t] += v;
        __syncthreads();
    }
    int run = (t == 0) ? 0 : part[t - 1];
    for (int i = beg; i < end; i++) {
        g_rowptr[i] = run;
        run += g_cnt[i];
        g_cnt[i] = 0;
    }
    if (t == 1023) g_rowptr[NN] = part[1023];
}
__global__ void fill_kernel(const int* __restrict__ src, const int* __restrict__ dst,
                            const float* __restrict__ w, int e) {
    int i = blockIdx.x * blockDim.x + threadIdx.x;
    if (i >= e) return;
    int s = src[i], d = dst[i];
    int pos = g_rowptr[d] + atomicAdd(&g_cnt[d], 1);
    g_ssrc[pos] = s;
    g_sw[pos] = g_deg[s] * w[i] * g_deg[d];
}

// ================= prep kernels =================
__global__ void prep_w_kernel(const float* __restrict__ Wg, const float* __restrict__ Ws,
                              int K, int NV, int NHALF,
                              __nv_bfloat16* __restrict__ hi, __nv_bfloat16* __restrict__ lo) {
    int idx = blockIdx.x * blockDim.x + threadIdx.x;
    int total = 2 * NHALF * K;
    if (idx >= total) return;
    int n = idx / K, k = idx - n * K;
    float v = 0.f;
    if (n < NHALF) { if (n < NV) v = Wg[k * NV + n]; }
    else { int c = n - NHALF; if (c < NV) v = Ws[k * NV + c]; }
    __nv_bfloat16 h = __float2bfloat16(v);
    hi[idx] = h;
    lo[idx] = __float2bfloat16(v - __bfloat162float(h));
}
__global__ void prep_b3_kernel(const float* __restrict__ b) {
    int i = threadIdx.x;
    if (i < NCLS_PAD) g_b3p[i] = (i < NCLS) ? b[i] : 0.f;
}
__global__ void split_kernel(const float* __restrict__ in,
                             __nv_bfloat16* __restrict__ hi, __nv_bfloat16* __restrict__ lo, int n) {
    int i = blockIdx.x * blockDim.x + threadIdx.x;
    if (i >= n) return;
    float v = in[i];
    __nv_bfloat16 h = __float2bfloat16(v);
    hi[i] = h;
    lo[i] = __float2bfloat16(v - __bfloat162float(h));
}

// ================= mma.sync bf16-split GEMM (as R3) =================
template<int K, int NHALF>
__global__ void __launch_bounds__(256, 1) gcn_gemm_mma(
    const __nv_bfloat16* __restrict__ Ahi, const __nv_bfloat16* __restrict__ Alo,
    const __nv_bfloat16* __restrict__ Whi, const __nv_bfloat16* __restrict__ Wlo,
    const float* __restrict__ bias,
    float* __restrict__ out_gcn, float* __restrict__ out_self, int nrows)
{
    constexpr int BK = 32;
    constexpr int NIT = K / BK;
    constexpr int ROWB = 80;
    constexpr int TILE = 128 * ROWB;

    __shared__ __align__(16) unsigned char sm[4 * TILE];

    const int tid = threadIdx.x;
    const int lane = tid & 31;
    const int wid = tid >> 5;
    const int row0 = blockIdx.x * 128;
    const int n0 = blockIdx.y * 128;
    const uint32_t sbase = smem_to_u32(sm);

    const int wm = wid >> 2;
    const int wn = wid & 3;
    const int m0w = wm * 64;
    const int n0w = wn * 32;

    float acc[4][4][4];
#pragma unroll
    for (int mt = 0; mt < 4; mt++)
#pragma unroll
        for (int nt = 0; nt < 4; nt++)
#pragma unroll
            for (int j = 0; j < 4; j++) acc[mt][nt][j] = 0.f;

    for (int kc = 0; kc < NIT; kc++) {
#pragma unroll
        for (int t = 0; t < 2; t++) {
            int i = tid + t * 256;
            int r = i >> 2, q = i & 3;
            size_t gcol = (size_t)kc * BK + q * 8;
            uint32_t soff = r * ROWB + q * 16;
            uint4 vh = make_uint4(0, 0, 0, 0), vl = make_uint4(0, 0, 0, 0);
            int grow = row0 + r;
            if (grow < nrows) {
                vh = *reinterpret_cast<const uint4*>(Ahi + (size_t)grow * K + gcol);
                vl = *reinterpret_cast<const uint4*>(Alo + (size_t)grow * K + gcol);
            }
            *reinterpret_cast<uint4*>(sm + soff)        = vh;
            *reinterpret_cast<uint4*>(sm + TILE + soff) = vl;
            int brow = n0 + r;
            uint4 wh = *reinterpret_cast<const uint4*>(Whi + (size_t)brow * K + gcol);
            uint4 wl = *reinterpret_cast<const uint4*>(Wlo + (size_t)brow * K + gcol);
            *reinterpret_cast<uint4*>(sm + 2 * TILE + soff) = wh;
            *reinterpret_cast<uint4*>(sm + 3 * TILE + soff) = wl;
        }
        __syncthreads();

#pragma unroll
        for (int ks = 0; ks < 2; ks++) {
            uint32_t ah[4][4], al[4][4], bh[4][2], bl[4][2];
#pragma unroll
            for (int mt = 0; mt < 4; mt++) {
                uint32_t addr = sbase +
                    (uint32_t)((m0w + mt * 16 + (lane & 15)) * ROWB + (ks * 2 + (lane >> 4)) * 16);
                LDSM_X4(ah[mt], addr);
                LDSM_X4(al[mt], addr + TILE);
            }
#pragma unroll
            for (int nt = 0; nt < 4; nt++) {
                uint32_t addr = sbase + 2 * TILE +
                    (uint32_t)((n0w + nt * 8 + (lane & 7)) * ROWB + (ks * 2 + ((lane >> 3) & 1)) * 16);
                LDSM_X2(bh[nt], addr);
                LDSM_X2(bl[nt], addr + TILE);
            }
#pragma unroll
            for (int mt = 0; mt < 4; mt++)
#pragma unroll
                for (int nt = 0; nt < 4; nt++) {
                    mma_bf16(acc[mt][nt], ah[mt], bh[nt]);
                    mma_bf16(acc[mt][nt], ah[mt], bl[nt]);
                    mma_bf16(acc[mt][nt], al[mt], bh[nt]);
                }
        }
        __syncthreads();
    }

#pragma unroll
    for (int mt = 0; mt < 4; mt++) {
        int rlo = row0 + m0w + mt * 16 + (lane >> 2);
        int rhi = rlo + 8;
#pragma unroll
        for (int nt = 0; nt < 4; nt++) {
            int gn = n0 + n0w + nt * 8 + (lane & 3) * 2;
            bool isg = gn < NHALF;
            int col = isg ? gn : gn - NHALF;
            float bx = 0.f, by = 0.f;
            float* base = isg ? out_gcn : out_self;
            if (!isg) { bx = __ldg(&bias[col]); by = __ldg(&bias[col + 1]); }
            if (rlo < nrows) {
                float2 v = make_float2(acc[mt][nt][0] + bx, acc[mt][nt][1] + by);
                *reinterpret_cast<float2*>(base + (size_t)rlo * NHALF + col) = v;
            }
            if (rhi < nrows) {
                float2 v = make_float2(acc[mt][nt][2] + bx, acc[mt][nt][3] + by);
                *reinterpret_cast<float2*>(base + (size_t)rhi * NHALF + col) = v;
            }
        }
    }
}

// ================= CSR aggregation + BN fused =================
// layers 1/2: one warp per dst node, F=128 (lane = float4 column)
// out = relu(BN(agg + self)) -> bf16 hi/lo split
__global__ void __launch_bounds__(256) agg_bn12_kernel(
    const float* __restrict__ hw, const float* __restrict__ selfacc,
    const float* __restrict__ gamma, const float* __restrict__ beta,
    const float* __restrict__ mean, const float* __restrict__ var,
    __nv_bfloat16* __restrict__ hi, __nv_bfloat16* __restrict__ lo)
{
    int v = (blockIdx.x * blockDim.x + threadIdx.x) >> 5;
    if (v >= NN) return;
    int lane = threadIdx.x & 31;
    int beg = g_rowptr[v], end = g_rowptr[v + 1];

    float4 acc = make_float4(0.f, 0.f, 0.f, 0.f);
    int e = beg;
    for (; e + 1 < end; e += 2) {
        int s0 = __ldg(&g_ssrc[e]);
        int s1 = __ldg(&g_ssrc[e + 1]);
        float w0 = __ldg(&g_sw[e]);
        float w1 = __ldg(&g_sw[e + 1]);
        float4 x0 = __ldg(reinterpret_cast<const float4*>(hw + (size_t)s0 * 128) + lane);
        float4 x1 = __ldg(reinterpret_cast<const float4*>(hw + (size_t)s1 * 128) + lane);
        acc.x += w0 * x0.x + w1 * x1.x;
        acc.y += w0 * x0.y + w1 * x1.y;
        acc.z += w0 * x0.z + w1 * x1.z;
        acc.w += w0 * x0.w + w1 * x1.w;
    }
    if (e < end) {
        int s0 = __ldg(&g_ssrc[e]);
        float w0 = __ldg(&g_sw[e]);
        float4 x0 = __ldg(reinterpret_cast<const float4*>(hw + (size_t)s0 * 128) + lane);
        acc.x += w0 * x0.x; acc.y += w0 * x0.y; acc.z += w0 * x0.z; acc.w += w0 * x0.w;
    }

    float4 sf = __ldg(reinterpret_cast<const float4*>(selfacc + (size_t)v * 128) + lane);
    int c = lane * 4;
    float vals[4] = { acc.x + sf.x, acc.y + sf.y, acc.z + sf.z, acc.w + sf.w };
    uint32_t hpack[2], lpack[2];
#pragma unroll
    for (int p = 0; p < 2; p++) {
        __nv_bfloat16 h2[2], l2[2];
#pragma unroll
        for (int j = 0; j < 2; j++) {
            int ch = c + p * 2 + j;
            float t = vals[p * 2 + j];
            t = (t - __ldg(&mean[ch])) * rsqrtf(__ldg(&var[ch]) + EPSBN) * __ldg(&gamma[ch]) + __ldg(&beta[ch]);
            t = fmaxf(t, 0.f);
            __nv_bfloat16 hh = __float2bfloat16(t);
            h2[j] = hh;
            l2[j] = __float2bfloat16(t - __bfloat162float(hh));
        }
        hpack[p] = (uint32_t)*reinterpret_cast<uint16_t*>(&h2[0]) |
                   ((uint32_t)*reinterpret_cast<uint16_t*>(&h2[1]) << 16);
        lpack[p] = (uint32_t)*reinterpret_cast<uint16_t*>(&l2[0]) |
                   ((uint32_t)*reinterpret_cast<uint16_t*>(&l2[1]) << 16);
    }
    *reinterpret_cast<uint2*>(hi + (size_t)v * 128 + c) = make_uint2(hpack[0], hpack[1]);
    *reinterpret_cast<uint2*>(lo + (size_t)v * 128 + c) = make_uint2(lpack[0], lpack[1]);
}

// layer 3: one warp per dst node, stride 64, 40 useful cols; BN no relu; fp32 out stride 40
__global__ void __launch_bounds__(256) agg_bn3_kernel(
    const float* __restrict__ hw, const float* __restrict__ selfacc,
    const float* __restrict__ gamma, const float* __restrict__ beta,
    const float* __restrict__ mean, const float* __restrict__ var,
    float* __restrict__ out)
{
    int v = (blockIdx.x * blockDim.x + threadIdx.x) >> 5;
    if (v >= NN) return;
    int lane = threadIdx.x & 31;
    if (lane >= 20) return;  // 40 cols / 2
    int beg = g_rowptr[v], end = g_rowptr[v + 1];

    float2 acc = make_float2(0.f, 0.f);
    int e = beg;
    for (; e + 1 < end; e += 2) {
        int s0 = __ldg(&g_ssrc[e]);
        int s1 = __ldg(&g_ssrc[e + 1]);
        float w0 = __ldg(&g_sw[e]);
        float w1 = __ldg(&g_sw[e + 1]);
        float2 x0 = __ldg(reinterpret_cast<const float2*>(hw + (size_t)s0 * NCLS_PAD) + lane);
        float2 x1 = __ldg(reinterpret_cast<const float2*>(hw + (size_t)s1 * NCLS_PAD) + lane);
        acc.x += w0 * x0.x + w1 * x1.x;
        acc.y += w0 * x0.y + w1 * x1.y;
    }
    if (e < end) {
        int s0 = __ldg(&g_ssrc[e]);
        float w0 = __ldg(&g_sw[e]);
        float2 x0 = __ldg(reinterpret_cast<const float2*>(hw + (size_t)s0 * NCLS_PAD) + lane);
        acc.x += w0 * x0.x;
        acc.y += w0 * x0.y;
    }

    float2 sf = __ldg(reinterpret_cast<const float2*>(selfacc + (size_t)v * NCLS_PAD) + lane);
    int c = lane * 2;
    float2 o;
    o.x = (acc.x + sf.x - __ldg(&mean[c]))     * rsqrtf(__ldg(&var[c]) + EPSBN)     * __ldg(&gamma[c])     + __ldg(&beta[c]);
    o.y = (acc.y + sf.y - __ldg(&mean[c + 1])) * rsqrtf(__ldg(&var[c + 1]) + EPSBN) * __ldg(&gamma[c + 1]) + __ldg(&beta[c + 1]);
    *reinterpret_cast<float2*>(out + (size_t)v * NCLS + c) = o;
}

// ================= launch =================
extern "C" void kernel_launch(void* const* d_in, const int* in_sizes, int n_in,
                              void* d_out, int out_size) {
    const float* x   = (const float*)d_in[0];
    const int*   ei  = (const int*)d_in[1];
    const float* ew  = (const float*)d_in[2];
    const int* src = ei;
    const int* dst = ei + EE;

    const float* wg1 = (const float*)d_in[3];
    const float* ws1 = (const float*)d_in[4];
    const float* b1  = (const float*)d_in[5];
    const float* gm1 = (const float*)d_in[6];
    const float* bt1 = (const float*)d_in[7];
    const float* mn1 = (const float*)d_in[8];
    const float* vr1 = (const float*)d_in[9];

    const float* wg2 = (const float*)d_in[10];
    const float* ws2 = (const float*)d_in[11];
    const float* b2  = (const float*)d_in[12];
    const float* gm2 = (const float*)d_in[13];
    const float* bt2 = (const float*)d_in[14];
    const float* mn2 = (const float*)d_in[15];
    const float* vr2 = (const float*)d_in[16];

    const float* wg3 = (const float*)d_in[17];
    const float* ws3 = (const float*)d_in[18];
    const float* b3  = (const float*)d_in[19];
    const float* gm3 = (const float*)d_in[20];
    const float* bt3 = (const float*)d_in[21];
    const float* mn3 = (const float*)d_in[22];
    const float* vr3 = (const float*)d_in[23];

    float* out = (float*)d_out;

    float *p_hw, *p_acc, *p_b3p;
    __nv_bfloat16 *p_xhi, *p_xlo, *p_hhi, *p_hlo;
    __nv_bfloat16 *p_w1hi, *p_w1lo, *p_w2hi, *p_w2lo, *p_w3hi, *p_w3lo;
    cudaGetSymbolAddress((void**)&p_hw,  g_hw);
    cudaGetSymbolAddress((void**)&p_acc, g_acc);
    cudaGetSymbolAddress((void**)&p_b3p, g_b3p);
    cudaGetSymbolAddress((void**)&p_xhi, g_xhi);
    cudaGetSymbolAddress((void**)&p_xlo, g_xlo);
    cudaGetSymbolAddress((void**)&p_hhi, g_hhi);
    cudaGetSymbolAddress((void**)&p_hlo, g_hlo);
    cudaGetSymbolAddress((void**)&p_w1hi, g_w1hi);
    cudaGetSymbolAddress((void**)&p_w1lo, g_w1lo);
    cudaGetSymbolAddress((void**)&p_w2hi, g_w2hi);
    cudaGetSymbolAddress((void**)&p_w2lo, g_w2lo);
    cudaGetSymbolAddress((void**)&p_w3hi, g_w3hi);
    cudaGetSymbolAddress((void**)&p_w3lo, g_w3lo);

    const int TPB = 256;
    const int GRID_M = (NN + 127) / 128;           // 391
    const int GRID_W = (NN * 32 + TPB - 1) / TPB;  // warp-per-node grids

    // ---- CSR build + normalization ----
    zero_dc_kernel<<<(NN + TPB - 1) / TPB, TPB>>>();
    count_deg_kernel<<<(EE + TPB - 1) / TPB, TPB>>>(dst, ew, EE);
    dinv_kernel<<<(NN + TPB - 1) / TPB, TPB>>>(NN);
    scan_kernel<<<1, 1024>>>();
    fill_kernel<<<(EE + TPB - 1) / TPB, TPB>>>(src, dst, ew, EE);

    // ---- prep: transposed bf16 hi/lo weights, x split ----
    prep_w_kernel<<<(2 * 128 * 256 + TPB - 1) / TPB, TPB>>>(wg1, ws1, 256, 128, 128, p_w1hi, p_w1lo);
    prep_w_kernel<<<(2 * 128 * 128 + TPB - 1) / TPB, TPB>>>(wg2, ws2, 128, 128, 128, p_w2hi, p_w2lo);
    prep_w_kernel<<<(2 * 64 * 128 + TPB - 1) / TPB, TPB>>>(wg3, ws3, 128, 40, 64, p_w3hi, p_w3lo);
    prep_b3_kernel<<<1, 64>>>(b3);
    split_kernel<<<(NN * F_IN + TPB - 1) / TPB, TPB>>>(x, p_xhi, p_xlo, NN * F_IN);

    // ---- layer 1 ----
    gcn_gemm_mma<256, 128><<<dim3(GRID_M, 2), 256>>>(p_xhi, p_xlo, p_w1hi, p_w1lo, b1, p_hw, p_acc, NN);
    agg_bn12_kernel<<<GRID_W, TPB>>>(p_hw, p_acc, gm1, bt1, mn1, vr1, p_hhi, p_hlo);

    // ---- layer 2 ----
    gcn_gemm_mma<128, 128><<<dim3(GRID_M, 2), 256>>>(p_hhi, p_hlo, p_w2hi, p_w2lo, b2, p_hw, p_acc, NN);
    agg_bn12_kernel<<<GRID_W, TPB>>>(p_hw, p_acc, gm2, bt2, mn2, vr2, p_hhi, p_hlo);

    // ---- layer 3 ----
    gcn_gemm_mma<128, 64><<<dim3(GRID_M, 1), 256>>>(p_hhi, p_hlo, p_w3hi, p_w3lo, p_b3p, p_hw, p_acc, NN);
    agg_bn3_kernel<<<GRID_W, TPB>>>(p_hw, p_acc, gm3, bt3, mn3, vr3, out);
}

// round 5
// speedup vs baseline: 1.7656x; 1.1906x over previous
#include <cuda_runtime.h>
#include <cuda_bf16.h>
#include <cstdint>

// Problem constants
#define NN 50000
#define EE 1000000
#define F_IN 256
#define UNITS 128
#define NCLS 40
#define NCLS_PAD 64
#define EPSBN 1e-3f

#define SCAN_B 256
#define NBLK ((NN + SCAN_B - 1) / SCAN_B)   // 196

// ================= mma.sync helpers =================
__device__ __forceinline__ uint32_t smem_to_u32(const void* p) {
    uint32_t a;
    asm("{ .reg .u64 t; cvta.to.shared.u64 t, %1; cvt.u32.u64 %0, t; }" : "=r"(a) : "l"(p));
    return a;
}
#define LDSM_X4(r, addr) \
    asm volatile("ldmatrix.sync.aligned.m8n8.x4.shared.b16 {%0,%1,%2,%3}, [%4];" \
        : "=r"((r)[0]), "=r"((r)[1]), "=r"((r)[2]), "=r"((r)[3]) : "r"(addr))
#define LDSM_X2(r, addr) \
    asm volatile("ldmatrix.sync.aligned.m8n8.x2.shared.b16 {%0,%1}, [%2];" \
        : "=r"((r)[0]), "=r"((r)[1]) : "r"(addr))

__device__ __forceinline__ void mma_bf16(float* c, const uint32_t* a, const uint32_t* b) {
    asm volatile("mma.sync.aligned.m16n8k16.row.col.f32.bf16.bf16.f32 "
        "{%0,%1,%2,%3}, {%4,%5,%6,%7}, {%8,%9}, {%0,%1,%2,%3};"
        : "+f"(c[0]), "+f"(c[1]), "+f"(c[2]), "+f"(c[3])
        : "r"(a[0]), "r"(a[1]), "r"(a[2]), "r"(a[3]), "r"(b[0]), "r"(b[1]));
}

// ================= scratch (static device globals) =================
__device__ __align__(16) float g_deg[NN];
__device__ __align__(16) int   g_cnt[NN];
__device__ __align__(16) int   g_rowptr[NN + 1];
__device__ __align__(16) int   g_bsum[NBLK];
__device__ __align__(16) int   g_boff[NBLK];
__device__ __align__(16) int   g_ssrc[EE];
__device__ __align__(16) float g_sw[EE];
__device__ __align__(16) float g_hw[(size_t)NN * 128];
__device__ __align__(16) float g_acc[(size_t)NN * 128];
__device__ __align__(16) __nv_bfloat16 g_xhi[(size_t)NN * F_IN];
__device__ __align__(16) __nv_bfloat16 g_xlo[(size_t)NN * F_IN];
__device__ __align__(16) __nv_bfloat16 g_hhi[(size_t)NN * 128];
__device__ __align__(16) __nv_bfloat16 g_hlo[(size_t)NN * 128];
__device__ __align__(16) __nv_bfloat16 g_w1hi[256 * 256];
__device__ __align__(16) __nv_bfloat16 g_w1lo[256 * 256];
__device__ __align__(16) __nv_bfloat16 g_w2hi[256 * 128];
__device__ __align__(16) __nv_bfloat16 g_w2lo[256 * 128];
__device__ __align__(16) __nv_bfloat16 g_w3hi[128 * 128];
__device__ __align__(16) __nv_bfloat16 g_w3lo[128 * 128];
__device__ __align__(16) float g_b3p[NCLS_PAD];

// ================= CSR build =================
__global__ void zero_dc_kernel() {
    int i = blockIdx.x * blockDim.x + threadIdx.x;
    if (i < NN) { g_deg[i] = 0.f; g_cnt[i] = 0; }
}
__global__ void count_deg_kernel(const int* __restrict__ dst, const float* __restrict__ w, int e) {
    int i = blockIdx.x * blockDim.x + threadIdx.x;
    if (i < e) {
        int d = dst[i];
        atomicAdd(&g_cnt[d], 1);
        atomicAdd(&g_deg[d], w[i]);
    }
}
__global__ void dinv_kernel(int n) {
    int i = blockIdx.x * blockDim.x + threadIdx.x;
    if (i < n) {
        float d = g_deg[i];
        g_deg[i] = (d > 0.f) ? rsqrtf(d) : 0.f;
    }
}

// ---- hierarchical scan: cnt -> rowptr (exclusive) ----
// level 1: per-block sums
__global__ void __launch_bounds__(SCAN_B) blocksum_kernel() {
    __shared__ int sh[SCAN_B];
    int i = blockIdx.x * SCAN_B + threadIdx.x;
    int v = (i < NN) ? g_cnt[i] : 0;
    sh[threadIdx.x] = v;
    __syncthreads();
    for (int off = SCAN_B / 2; off > 0; off >>= 1) {
        if (threadIdx.x < off) sh[threadIdx.x] += sh[threadIdx.x + off];
        __syncthreads();
    }
    if (threadIdx.x == 0) g_bsum[blockIdx.x] = sh[0];
}
// level 2: one small block scans NBLK sums -> exclusive offsets + total
__global__ void __launch_bounds__(SCAN_B) scan_bsum_kernel() {
    __shared__ int sh[SCAN_B];
    int t = threadIdx.x;
    int v = (t < NBLK) ? g_bsum[t] : 0;
    sh[t] = v;
    __syncthreads();
    for (int off = 1; off < SCAN_B; off <<= 1) {
        int u = (t >= off) ? sh[t - off] : 0;
        __syncthreads();
        sh[t] += u;
        __syncthreads();
    }
    if (t < NBLK) g_boff[t] = sh[t] - v;          // exclusive
    if (t == SCAN_B - 1) g_rowptr[NN] = sh[SCAN_B - 1];
}
// level 3: per-block exclusive scan + offset -> rowptr, zero cnt
__global__ void __launch_bounds__(SCAN_B) scatter_rowptr_kernel() {
    __shared__ int sh[SCAN_B];
    int i = blockIdx.x * SCAN_B + threadIdx.x;
    int t = threadIdx.x;
    int v = (i < NN) ? g_cnt[i] : 0;
    sh[t] = v;
    __syncthreads();
    for (int off = 1; off < SCAN_B; off <<= 1) {
        int u = (t >= off) ? sh[t - off] : 0;
        __syncthreads();
        sh[t] += u;
        __syncthreads();
    }
    if (i < NN) {
        g_rowptr[i] = g_boff[blockIdx.x] + sh[t] - v;
        g_cnt[i] = 0;
    }
}
__global__ void fill_kernel(const int* __restrict__ src, const int* __restrict__ dst,
                            const float* __restrict__ w, int e) {
    int i = blockIdx.x * blockDim.x + threadIdx.x;
    if (i >= e) return;
    int s = src[i], d = dst[i];
    int pos = g_rowptr[d] + atomicAdd(&g_cnt[d], 1);
    g_ssrc[pos] = s;
    g_sw[pos] = g_deg[s] * w[i] * g_deg[d];
}

// ================= prep kernels =================
__global__ void prep_w_kernel(const float* __restrict__ Wg, const float* __restrict__ Ws,
                              int K, int NV, int NHALF,
                              __nv_bfloat16* __restrict__ hi, __nv_bfloat16* __restrict__ lo) {
    int idx = blockIdx.x * blockDim.x + threadIdx.x;
    int total = 2 * NHALF * K;
    if (idx >= total) return;
    int n = idx / K, k = idx - n * K;
    float v = 0.f;
    if (n < NHALF) { if (n < NV) v = Wg[k * NV + n]; }
    else { int c = n - NHALF; if (c < NV) v = Ws[k * NV + c]; }
    __nv_bfloat16 h = __float2bfloat16(v);
    hi[idx] = h;
    lo[idx] = __float2bfloat16(v - __bfloat162float(h));
}
__global__ void prep_b3_kernel(const float* __restrict__ b) {
    int i = threadIdx.x;
    if (i < NCLS_PAD) g_b3p[i] = (i < NCLS) ? b[i] : 0.f;
}
__global__ void split_kernel(const float* __restrict__ in,
                             __nv_bfloat16* __restrict__ hi, __nv_bfloat16* __restrict__ lo, int n) {
    int i = blockIdx.x * blockDim.x + threadIdx.x;
    if (i >= n) return;
    float v = in[i];
    __nv_bfloat16 h = __float2bfloat16(v);
    hi[i] = h;
    lo[i] = __float2bfloat16(v - __bfloat162float(h));
}

// ================= mma.sync bf16-split GEMM =================
template<int K, int NHALF>
__global__ void __launch_bounds__(256, 1) gcn_gemm_mma(
    const __nv_bfloat16* __restrict__ Ahi, const __nv_bfloat16* __restrict__ Alo,
    const __nv_bfloat16* __restrict__ Whi, const __nv_bfloat16* __restrict__ Wlo,
    const float* __restrict__ bias,
    float* __restrict__ out_gcn, float* __restrict__ out_self, int nrows)
{
    constexpr int BK = 32;
    constexpr int NIT = K / BK;
    constexpr int ROWB = 80;
    constexpr int TILE = 128 * ROWB;

    __shared__ __align__(16) unsigned char sm[4 * TILE];

    const int tid = threadIdx.x;
    const int lane = tid & 31;
    const int wid = tid >> 5;
    const int row0 = blockIdx.x * 128;
    const int n0 = blockIdx.y * 128;
    const uint32_t sbase = smem_to_u32(sm);

    const int wm = wid >> 2;
    const int wn = wid & 3;
    const int m0w = wm * 64;
    const int n0w = wn * 32;

    float acc[4][4][4];
#pragma unroll
    for (int mt = 0; mt < 4; mt++)
#pragma unroll
        for (int nt = 0; nt < 4; nt++)
#pragma unroll
            for (int j = 0; j < 4; j++) acc[mt][nt][j] = 0.f;

    for (int kc = 0; kc < NIT; kc++) {
#pragma unroll
        for (int t = 0; t < 2; t++) {
            int i = tid + t * 256;
            int r = i >> 2, q = i & 3;
            size_t gcol = (size_t)kc * BK + q * 8;
            uint32_t soff = r * ROWB + q * 16;
            uint4 vh = make_uint4(0, 0, 0, 0), vl = make_uint4(0, 0, 0, 0);
            int grow = row0 + r;
            if (grow < nrows) {
                vh = *reinterpret_cast<const uint4*>(Ahi + (size_t)grow * K + gcol);
                vl = *reinterpret_cast<const uint4*>(Alo + (size_t)grow * K + gcol);
            }
            *reinterpret_cast<uint4*>(sm + soff)        = vh;
            *reinterpret_cast<uint4*>(sm + TILE + soff) = vl;
            int brow = n0 + r;
            uint4 wh = *reinterpret_cast<const uint4*>(Whi + (size_t)brow * K + gcol);
            uint4 wl = *reinterpret_cast<const uint4*>(Wlo + (size_t)brow * K + gcol);
            *reinterpret_cast<uint4*>(sm + 2 * TILE + soff) = wh;
            *reinterpret_cast<uint4*>(sm + 3 * TILE + soff) = wl;
        }
        __syncthreads();

#pragma unroll
        for (int ks = 0; ks < 2; ks++) {
            uint32_t ah[4][4], al[4][4], bh[4][2], bl[4][2];
#pragma unroll
            for (int mt = 0; mt < 4; mt++) {
                uint32_t addr = sbase +
                    (uint32_t)((m0w + mt * 16 + (lane & 15)) * ROWB + (ks * 2 + (lane >> 4)) * 16);
                LDSM_X4(ah[mt], addr);
                LDSM_X4(al[mt], addr + TILE);
            }
#pragma unroll
            for (int nt = 0; nt < 4; nt++) {
                uint32_t addr = sbase + 2 * TILE +
                    (uint32_t)((n0w + nt * 8 + (lane & 7)) * ROWB + (ks * 2 + ((lane >> 3) & 1)) * 16);
                LDSM_X2(bh[nt], addr);
                LDSM_X2(bl[nt], addr + TILE);
            }
#pragma unroll
            for (int mt = 0; mt < 4; mt++)
#pragma unroll
                for (int nt = 0; nt < 4; nt++) {
                    mma_bf16(acc[mt][nt], ah[mt], bh[nt]);
                    mma_bf16(acc[mt][nt], ah[mt], bl[nt]);
                    mma_bf16(acc[mt][nt], al[mt], bh[nt]);
                }
        }
        __syncthreads();
    }

#pragma unroll
    for (int mt = 0; mt < 4; mt++) {
        int rlo = row0 + m0w + mt * 16 + (lane >> 2);
        int rhi = rlo + 8;
#pragma unroll
        for (int nt = 0; nt < 4; nt++) {
            int gn = n0 + n0w + nt * 8 + (lane & 3) * 2;
            bool isg = gn < NHALF;
            int col = isg ? gn : gn - NHALF;
            float bx = 0.f, by = 0.f;
            float* base = isg ? out_gcn : out_self;
            if (!isg) { bx = __ldg(&bias[col]); by = __ldg(&bias[col + 1]); }
            if (rlo < nrows) {
                float2 v = make_float2(acc[mt][nt][0] + bx, acc[mt][nt][1] + by);
                *reinterpret_cast<float2*>(base + (size_t)rlo * NHALF + col) = v;
            }
            if (rhi < nrows) {
                float2 v = make_float2(acc[mt][nt][2] + bx, acc[mt][nt][3] + by);
                *reinterpret_cast<float2*>(base + (size_t)rhi * NHALF + col) = v;
            }
        }
    }
}

// ================= CSR aggregation + BN fused =================
__global__ void __launch_bounds__(256) agg_bn12_kernel(
    const float* __restrict__ hw, const float* __restrict__ selfacc,
    const float* __restrict__ gamma, const float* __restrict__ beta,
    const float* __restrict__ mean, const float* __restrict__ var,
    __nv_bfloat16* __restrict__ hi, __nv_bfloat16* __restrict__ lo)
{
    int v = (blockIdx.x * blockDim.x + threadIdx.x) >> 5;
    if (v >= NN) return;
    int lane = threadIdx.x & 31;
    int beg = g_rowptr[v], end = g_rowptr[v + 1];

    float4 acc = make_float4(0.f, 0.f, 0.f, 0.f);
    int e = beg;
    for (; e + 1 < end; e += 2) {
        int s0 = __ldg(&g_ssrc[e]);
        int s1 = __ldg(&g_ssrc[e + 1]);
        float w0 = __ldg(&g_sw[e]);
        float w1 = __ldg(&g_sw[e + 1]);
        float4 x0 = __ldg(reinterpret_cast<const float4*>(hw + (size_t)s0 * 128) + lane);
        float4 x1 = __ldg(reinterpret_cast<const float4*>(hw + (size_t)s1 * 128) + lane);
        acc.x += w0 * x0.x + w1 * x1.x;
        acc.y += w0 * x0.y + w1 * x1.y;
        acc.z += w0 * x0.z + w1 * x1.z;
        acc.w += w0 * x0.w + w1 * x1.w;
    }
    if (e < end) {
        int s0 = __ldg(&g_ssrc[e]);
        float w0 = __ldg(&g_sw[e]);
        float4 x0 = __ldg(reinterpret_cast<const float4*>(hw + (size_t)s0 * 128) + lane);
        acc.x += w0 * x0.x; acc.y += w0 * x0.y; acc.z += w0 * x0.z; acc.w += w0 * x0.w;
    }

    float4 sf = __ldg(reinterpret_cast<const float4*>(selfacc + (size_t)v * 128) + lane);
    int c = lane * 4;
    float vals[4] = { acc.x + sf.x, acc.y + sf.y, acc.z + sf.z, acc.w + sf.w };
    uint32_t hpack[2], lpack[2];
#pragma unroll
    for (int p = 0; p < 2; p++) {
        __nv_bfloat16 h2[2], l2[2];
#pragma unroll
        for (int j = 0; j < 2; j++) {
            int ch = c + p * 2 + j;
            float t = vals[p * 2 + j];
            t = (t - __ldg(&mean[ch])) * rsqrtf(__ldg(&var[ch]) + EPSBN) * __ldg(&gamma[ch]) + __ldg(&beta[ch]);
            t = fmaxf(t, 0.f);
            __nv_bfloat16 hh = __float2bfloat16(t);
            h2[j] = hh;
            l2[j] = __float2bfloat16(t - __bfloat162float(hh));
        }
        hpack[p] = (uint32_t)*reinterpret_cast<uint16_t*>(&h2[0]) |
                   ((uint32_t)*reinterpret_cast<uint16_t*>(&h2[1]) << 16);
        lpack[p] = (uint32_t)*reinterpret_cast<uint16_t*>(&l2[0]) |
                   ((uint32_t)*reinterpret_cast<uint16_t*>(&l2[1]) << 16);
    }
    *reinterpret_cast<uint2*>(hi + (size_t)v * 128 + c) = make_uint2(hpack[0], hpack[1]);
    *reinterpret_cast<uint2*>(lo + (size_t)v * 128 + c) = make_uint2(lpack[0], lpack[1]);
}

__global__ void __launch_bounds__(256) agg_bn3_kernel(
    const float* __restrict__ hw, const float* __restrict__ selfacc,
    const float* __restrict__ gamma, const float* __restrict__ beta,
    const float* __restrict__ mean, const float* __restrict__ var,
    float* __restrict__ out)
{
    int v = (blockIdx.x * blockDim.x + threadIdx.x) >> 5;
    if (v >= NN) return;
    int lane = threadIdx.x & 31;
    if (lane >= 20) return;
    int beg = g_rowptr[v], end = g_rowptr[v + 1];

    float2 acc = make_float2(0.f, 0.f);
    int e = beg;
    for (; e + 1 < end; e += 2) {
        int s0 = __ldg(&g_ssrc[e]);
        int s1 = __ldg(&g_ssrc[e + 1]);
        float w0 = __ldg(&g_sw[e]);
        float w1 = __ldg(&g_sw[e + 1]);
        float2 x0 = __ldg(reinterpret_cast<const float2*>(hw + (size_t)s0 * NCLS_PAD) + lane);
        float2 x1 = __ldg(reinterpret_cast<const float2*>(hw + (size_t)s1 * NCLS_PAD) + lane);
        acc.x += w0 * x0.x + w1 * x1.x;
        acc.y += w0 * x0.y + w1 * x1.y;
    }
    if (e < end) {
        int s0 = __ldg(&g_ssrc[e]);
        float w0 = __ldg(&g_sw[e]);
        float2 x0 = __ldg(reinterpret_cast<const float2*>(hw + (size_t)s0 * NCLS_PAD) + lane);
        acc.x += w0 * x0.x;
        acc.y += w0 * x0.y;
    }

    float2 sf = __ldg(reinterpret_cast<const float2*>(selfacc + (size_t)v * NCLS_PAD) + lane);
    int c = lane * 2;
    float2 o;
    o.x = (acc.x + sf.x - __ldg(&mean[c]))     * rsqrtf(__ldg(&var[c]) + EPSBN)     * __ldg(&gamma[c])     + __ldg(&beta[c]);
    o.y = (acc.y + sf.y - __ldg(&mean[c + 1])) * rsqrtf(__ldg(&var[c + 1]) + EPSBN) * __ldg(&gamma[c + 1]) + __ldg(&beta[c + 1]);
    *reinterpret_cast<float2*>(out + (size_t)v * NCLS + c) = o;
}

// ================= launch =================
extern "C" void kernel_launch(void* const* d_in, const int* in_sizes, int n_in,
                              void* d_out, int out_size) {
    const float* x   = (const float*)d_in[0];
    const int*   ei  = (const int*)d_in[1];
    const float* ew  = (const float*)d_in[2];
    const int* src = ei;
    const int* dst = ei + EE;

    const float* wg1 = (const float*)d_in[3];
    const float* ws1 = (const float*)d_in[4];
    const float* b1  = (const float*)d_in[5];
    const float* gm1 = (const float*)d_in[6];
    const float* bt1 = (const float*)d_in[7];
    const float* mn1 = (const float*)d_in[8];
    const float* vr1 = (const float*)d_in[9];

    const float* wg2 = (const float*)d_in[10];
    const float* ws2 = (const float*)d_in[11];
    const float* b2  = (const float*)d_in[12];
    const float* gm2 = (const float*)d_in[13];
    const float* bt2 = (const float*)d_in[14];
    const float* mn2 = (const float*)d_in[15];
    const float* vr2 = (const float*)d_in[16];

    const float* wg3 = (const float*)d_in[17];
    const float* ws3 = (const float*)d_in[18];
    const float* b3  = (const float*)d_in[19];
    const float* gm3 = (const float*)d_in[20];
    const float* bt3 = (const float*)d_in[21];
    const float* mn3 = (const float*)d_in[22];
    const float* vr3 = (const float*)d_in[23];

    float* out = (float*)d_out;

    float *p_hw, *p_acc, *p_b3p;
    __nv_bfloat16 *p_xhi, *p_xlo, *p_hhi, *p_hlo;
    __nv_bfloat16 *p_w1hi, *p_w1lo, *p_w2hi, *p_w2lo, *p_w3hi, *p_w3lo;
    cudaGetSymbolAddress((void**)&p_hw,  g_hw);
    cudaGetSymbolAddress((void**)&p_acc, g_acc);
    cudaGetSymbolAddress((void**)&p_b3p, g_b3p);
    cudaGetSymbolAddress((void**)&p_xhi, g_xhi);
    cudaGetSymbolAddress((void**)&p_xlo, g_xlo);
    cudaGetSymbolAddress((void**)&p_hhi, g_hhi);
    cudaGetSymbolAddress((void**)&p_hlo, g_hlo);
    cudaGetSymbolAddress((void**)&p_w1hi, g_w1hi);
    cudaGetSymbolAddress((void**)&p_w1lo, g_w1lo);
    cudaGetSymbolAddress((void**)&p_w2hi, g_w2hi);
    cudaGetSymbolAddress((void**)&p_w2lo, g_w2lo);
    cudaGetSymbolAddress((void**)&p_w3hi, g_w3hi);
    cudaGetSymbolAddress((void**)&p_w3lo, g_w3lo);

    const int TPB = 256;
    const int GRID_M = (NN + 127) / 128;           // 391
    const int GRID_W = (NN * 32 + TPB - 1) / TPB;  // warp-per-node grids

    // ---- CSR build + normalization ----
    zero_dc_kernel<<<(NN + TPB - 1) / TPB, TPB>>>();
    count_deg_kernel<<<(EE + TPB - 1) / TPB, TPB>>>(dst, ew, EE);
    dinv_kernel<<<(NN + TPB - 1) / TPB, TPB>>>(NN);
    blocksum_kernel<<<NBLK, SCAN_B>>>();
    scan_bsum_kernel<<<1, SCAN_B>>>();
    scatter_rowptr_kernel<<<NBLK, SCAN_B>>>();
    fill_kernel<<<(EE + TPB - 1) / TPB, TPB>>>(src, dst, ew, EE);

    // ---- prep: transposed bf16 hi/lo weights, x split ----
    prep_w_kernel<<<(2 * 128 * 256 + TPB - 1) / TPB, TPB>>>(wg1, ws1, 256, 128, 128, p_w1hi, p_w1lo);
    prep_w_kernel<<<(2 * 128 * 128 + TPB - 1) / TPB, TPB>>>(wg2, ws2, 128, 128, 128, p_w2hi, p_w2lo);
    prep_w_kernel<<<(2 * 64 * 128 + TPB - 1) / TPB, TPB>>>(wg3, ws3, 128, 40, 64, p_w3hi, p_w3lo);
    prep_b3_kernel<<<1, 64>>>(b3);
    split_kernel<<<(NN * F_IN + TPB - 1) / TPB, TPB>>>(x, p_xhi, p_xlo, NN * F_IN);

    // ---- layer 1 ----
    gcn_gemm_mma<256, 128><<<dim3(GRID_M, 2), 256>>>(p_xhi, p_xlo, p_w1hi, p_w1lo, b1, p_hw, p_acc, NN);
    agg_bn12_kernel<<<GRID_W, TPB>>>(p_hw, p_acc, gm1, bt1, mn1, vr1, p_hhi, p_hlo);

    // ---- layer 2 ----
    gcn_gemm_mma<128, 128><<<dim3(GRID_M, 2), 256>>>(p_hhi, p_hlo, p_w2hi, p_w2lo, b2, p_hw, p_acc, NN);
    agg_bn12_kernel<<<GRID_W, TPB>>>(p_hw, p_acc, gm2, bt2, mn2, vr2, p_hhi, p_hlo);

    // ---- layer 3 ----
    gcn_gemm_mma<128, 64><<<dim3(GRID_M, 1), 256>>>(p_hhi, p_hlo, p_w3hi, p_w3lo, p_b3p, p_hw, p_acc, NN);
    agg_bn3_kernel<<<GRID_W, TPB>>>(p_hw, p_acc, gm3, bt3, mn3, vr3, out);
}

// round 6
// speedup vs baseline: 1.8976x; 1.0747x over previous
#include <cuda_runtime.h>
#include <cuda_bf16.h>
#include <cstdint>

// Problem constants
#define NN 50000
#define EE 1000000
#define F_IN 256
#define UNITS 128
#define NCLS 40
#define NCLS_PAD 64
#define EPSBN 1e-3f

#define SCAN_B 256
#define NBLK ((NN + SCAN_B - 1) / SCAN_B)   // 196

// ================= mma.sync / cp.async helpers =================
__device__ __forceinline__ uint32_t smem_to_u32(const void* p) {
    uint32_t a;
    asm("{ .reg .u64 t; cvta.to.shared.u64 t, %1; cvt.u32.u64 %0, t; }" : "=r"(a) : "l"(p));
    return a;
}
#define LDSM_X4(r, addr) \
    asm volatile("ldmatrix.sync.aligned.m8n8.x4.shared.b16 {%0,%1,%2,%3}, [%4];" \
        : "=r"((r)[0]), "=r"((r)[1]), "=r"((r)[2]), "=r"((r)[3]) : "r"(addr))
#define LDSM_X2(r, addr) \
    asm volatile("ldmatrix.sync.aligned.m8n8.x2.shared.b16 {%0,%1}, [%2];" \
        : "=r"((r)[0]), "=r"((r)[1]) : "r"(addr))

__device__ __forceinline__ void mma_bf16(float* c, const uint32_t* a, const uint32_t* b) {
    asm volatile("mma.sync.aligned.m16n8k16.row.col.f32.bf16.bf16.f32 "
        "{%0,%1,%2,%3}, {%4,%5,%6,%7}, {%8,%9}, {%0,%1,%2,%3};"
        : "+f"(c[0]), "+f"(c[1]), "+f"(c[2]), "+f"(c[3])
        : "r"(a[0]), "r"(a[1]), "r"(a[2]), "r"(a[3]), "r"(b[0]), "r"(b[1]));
}
__device__ __forceinline__ void cp_async16(uint32_t sa, const void* g, uint32_t pbytes) {
    asm volatile("cp.async.cg.shared.global [%0], [%1], 16, %2;"
                 :: "r"(sa), "l"(g), "r"(pbytes) : "memory");
}
#define CP_COMMIT() asm volatile("cp.async.commit_group;" ::: "memory")
#define CP_WAIT0()  asm volatile("cp.async.wait_group 0;" ::: "memory")
#define CP_WAIT1()  asm volatile("cp.async.wait_group 1;" ::: "memory")

// ================= scratch (static device globals) =================
__device__ __align__(16) float g_deg[NN];
__device__ __align__(16) int   g_cnt[NN];
__device__ __align__(16) int   g_rowptr[NN + 1];
__device__ __align__(16) int   g_bsum[NBLK];
__device__ __align__(16) int   g_boff[NBLK];
__device__ __align__(16) int   g_ssrc[EE];
__device__ __align__(16) float g_sw[EE];
__device__ __align__(16) float g_hw[(size_t)NN * 128];
__device__ __align__(16) float g_acc[(size_t)NN * 128];
__device__ __align__(16) __nv_bfloat16 g_xhi[(size_t)NN * F_IN];
__device__ __align__(16) __nv_bfloat16 g_xlo[(size_t)NN * F_IN];
__device__ __align__(16) __nv_bfloat16 g_hhi[(size_t)NN * 128];
__device__ __align__(16) __nv_bfloat16 g_hlo[(size_t)NN * 128];
__device__ __align__(16) __nv_bfloat16 g_w1hi[256 * 256];
__device__ __align__(16) __nv_bfloat16 g_w1lo[256 * 256];
__device__ __align__(16) __nv_bfloat16 g_w2hi[256 * 128];
__device__ __align__(16) __nv_bfloat16 g_w2lo[256 * 128];
__device__ __align__(16) __nv_bfloat16 g_w3hi[128 * 128];
__device__ __align__(16) __nv_bfloat16 g_w3lo[128 * 128];
__device__ __align__(16) float g_b3p[NCLS_PAD];

// ================= CSR build =================
__global__ void zero_dc_kernel() {
    int i = blockIdx.x * blockDim.x + threadIdx.x;
    if (i < NN) { g_deg[i] = 0.f; g_cnt[i] = 0; }
}
__global__ void count_deg_kernel(const int* __restrict__ dst, const float* __restrict__ w, int e) {
    int i = blockIdx.x * blockDim.x + threadIdx.x;
    if (i < e) {
        int d = dst[i];
        atomicAdd(&g_cnt[d], 1);
        atomicAdd(&g_deg[d], w[i]);
    }
}
__global__ void dinv_kernel(int n) {
    int i = blockIdx.x * blockDim.x + threadIdx.x;
    if (i < n) {
        float d = g_deg[i];
        g_deg[i] = (d > 0.f) ? rsqrtf(d) : 0.f;
    }
}
__global__ void __launch_bounds__(SCAN_B) blocksum_kernel() {
    __shared__ int sh[SCAN_B];
    int i = blockIdx.x * SCAN_B + threadIdx.x;
    int v = (i < NN) ? g_cnt[i] : 0;
    sh[threadIdx.x] = v;
    __syncthreads();
    for (int off = SCAN_B / 2; off > 0; off >>= 1) {
        if (threadIdx.x < off) sh[threadIdx.x] += sh[threadIdx.x + off];
        __syncthreads();
    }
    if (threadIdx.x == 0) g_bsum[blockIdx.x] = sh[0];
}
__global__ void __launch_bounds__(SCAN_B) scan_bsum_kernel() {
    __shared__ int sh[SCAN_B];
    int t = threadIdx.x;
    int v = (t < NBLK) ? g_bsum[t] : 0;
    sh[t] = v;
    __syncthreads();
    for (int off = 1; off < SCAN_B; off <<= 1) {
        int u = (t >= off) ? sh[t - off] : 0;
        __syncthreads();
        sh[t] += u;
        __syncthreads();
    }
    if (t < NBLK) g_boff[t] = sh[t] - v;
    if (t == SCAN_B - 1) g_rowptr[NN] = sh[SCAN_B - 1];
}
__global__ void __launch_bounds__(SCAN_B) scatter_rowptr_kernel() {
    __shared__ int sh[SCAN_B];
    int i = blockIdx.x * SCAN_B + threadIdx.x;
    int t = threadIdx.x;
    int v = (i < NN) ? g_cnt[i] : 0;
    sh[t] = v;
    __syncthreads();
    for (int off = 1; off < SCAN_B; off <<= 1) {
        int u = (t >= off) ? sh[t - off] : 0;
        __syncthreads();
        sh[t] += u;
        __syncthreads();
    }
    if (i < NN) {
        g_rowptr[i] = g_boff[blockIdx.x] + sh[t] - v;
        g_cnt[i] = 0;
    }
}
__global__ void fill_kernel(const int* __restrict__ src, const int* __restrict__ dst,
                            const float* __restrict__ w, int e) {
    int i = blockIdx.x * blockDim.x + threadIdx.x;
    if (i >= e) return;
    int s = src[i], d = dst[i];
    int pos = g_rowptr[d] + atomicAdd(&g_cnt[d], 1);
    g_ssrc[pos] = s;
    g_sw[pos] = g_deg[s] * w[i] * g_deg[d];
}

// ================= prep kernels =================
__global__ void prep_w_kernel(const float* __restrict__ Wg, const float* __restrict__ Ws,
                              int K, int NV, int NHALF,
                              __nv_bfloat16* __restrict__ hi, __nv_bfloat16* __restrict__ lo) {
    int idx = blockIdx.x * blockDim.x + threadIdx.x;
    int total = 2 * NHALF * K;
    if (idx >= total) return;
    int n = idx / K, k = idx - n * K;
    float v = 0.f;
    if (n < NHALF) { if (n < NV) v = Wg[k * NV + n]; }
    else { int c = n - NHALF; if (c < NV) v = Ws[k * NV + c]; }
    __nv_bfloat16 h = __float2bfloat16(v);
    hi[idx] = h;
    lo[idx] = __float2bfloat16(v - __bfloat162float(h));
}
__global__ void prep_b3_kernel(const float* __restrict__ b) {
    int i = threadIdx.x;
    if (i < NCLS_PAD) g_b3p[i] = (i < NCLS) ? b[i] : 0.f;
}
__global__ void split_kernel(const float* __restrict__ in,
                             __nv_bfloat16* __restrict__ hi, __nv_bfloat16* __restrict__ lo, int n) {
    int i = blockIdx.x * blockDim.x + threadIdx.x;
    if (i >= n) return;
    float v = in[i];
    __nv_bfloat16 h = __float2bfloat16(v);
    hi[i] = h;
    lo[i] = __float2bfloat16(v - __bfloat162float(h));
}

// ================= cp.async double-buffered bf16-split GEMM =================
template<int K, int NHALF>
__global__ void __launch_bounds__(256, 1) gcn_gemm_mma(
    const __nv_bfloat16* __restrict__ Ahi, const __nv_bfloat16* __restrict__ Alo,
    const __nv_bfloat16* __restrict__ Whi, const __nv_bfloat16* __restrict__ Wlo,
    const float* __restrict__ bias,
    float* __restrict__ out_gcn, float* __restrict__ out_self, int nrows)
{
    constexpr int BK = 32;
    constexpr int NIT = K / BK;
    constexpr int ROWB = 80;
    constexpr int TILE = 128 * ROWB;    // 10240 B per tensor per stage
    constexpr int STAGE = 4 * TILE;     // Ahi | Alo | Bhi | Blo

    extern __shared__ __align__(16) unsigned char sm[];  // 2 * STAGE

    const int tid = threadIdx.x;
    const int lane = tid & 31;
    const int wid = tid >> 5;
    const int row0 = blockIdx.x * 128;
    const int n0 = blockIdx.y * 128;
    const uint32_t sbase = smem_to_u32(sm);

    const int wm = wid >> 2;
    const int wn = wid & 3;
    const int m0w = wm * 64;
    const int n0w = wn * 32;

    float acc[4][4][4];
#pragma unroll
    for (int mt = 0; mt < 4; mt++)
#pragma unroll
        for (int nt = 0; nt < 4; nt++)
#pragma unroll
            for (int j = 0; j < 4; j++) acc[mt][nt][j] = 0.f;

    // async stage loader: 8 cp.async x 16B per thread
    auto load_stage = [&](int kc, int st) {
#pragma unroll
        for (int t = 0; t < 2; t++) {
            int i = tid + t * 256;
            int r = i >> 2, q = i & 3;
            size_t gcol = (size_t)kc * BK + q * 8;
            uint32_t sa = sbase + st * STAGE + (uint32_t)(r * ROWB + q * 16);
            int grow = row0 + r;
            uint32_t pb = (grow < nrows) ? 16u : 0u;
            int gr = (grow < nrows) ? grow : 0;
            cp_async16(sa,            Ahi + (size_t)gr * K + gcol, pb);
            cp_async16(sa + TILE,     Alo + (size_t)gr * K + gcol, pb);
            int brow = n0 + r;
            cp_async16(sa + 2 * TILE, Whi + (size_t)brow * K + gcol, 16u);
            cp_async16(sa + 3 * TILE, Wlo + (size_t)brow * K + gcol, 16u);
        }
    };

    load_stage(0, 0);
    CP_COMMIT();

    for (int kc = 0; kc < NIT; kc++) {
        if (kc + 1 < NIT) {
            load_stage(kc + 1, (kc + 1) & 1);
            CP_COMMIT();
            CP_WAIT1();
        } else {
            CP_WAIT0();
        }
        __syncthreads();

        uint32_t stoff = (uint32_t)((kc & 1) * STAGE);
#pragma unroll
        for (int ks = 0; ks < 2; ks++) {
            uint32_t ah[4][4], al[4][4], bh[4][2], bl[4][2];
#pragma unroll
            for (int mt = 0; mt < 4; mt++) {
                uint32_t addr = sbase + stoff +
                    (uint32_t)((m0w + mt * 16 + (lane & 15)) * ROWB + (ks * 2 + (lane >> 4)) * 16);
                LDSM_X4(ah[mt], addr);
                LDSM_X4(al[mt], addr + TILE);
            }
#pragma unroll
            for (int nt = 0; nt < 4; nt++) {
                uint32_t addr = sbase + stoff + 2 * TILE +
                    (uint32_t)((n0w + nt * 8 + (lane & 7)) * ROWB + (ks * 2 + ((lane >> 3) & 1)) * 16);
                LDSM_X2(bh[nt], addr);
                LDSM_X2(bl[nt], addr + TILE);
            }
#pragma unroll
            for (int mt = 0; mt < 4; mt++)
#pragma unroll
                for (int nt = 0; nt < 4; nt++) {
                    mma_bf16(acc[mt][nt], ah[mt], bh[nt]);
                    mma_bf16(acc[mt][nt], ah[mt], bl[nt]);
                    mma_bf16(acc[mt][nt], al[mt], bh[nt]);
                }
        }
        __syncthreads();
    }

#pragma unroll
    for (int mt = 0; mt < 4; mt++) {
        int rlo = row0 + m0w + mt * 16 + (lane >> 2);
        int rhi = rlo + 8;
#pragma unroll
        for (int nt = 0; nt < 4; nt++) {
            int gn = n0 + n0w + nt * 8 + (lane & 3) * 2;
            bool isg = gn < NHALF;
            int col = isg ? gn : gn - NHALF;
            float bx = 0.f, by = 0.f;
            float* base = isg ? out_gcn : out_self;
            if (!isg) { bx = __ldg(&bias[col]); by = __ldg(&bias[col + 1]); }
            if (rlo < nrows) {
                float2 v = make_float2(acc[mt][nt][0] + bx, acc[mt][nt][1] + by);
                *reinterpret_cast<float2*>(base + (size_t)rlo * NHALF + col) = v;
            }
            if (rhi < nrows) {
                float2 v = make_float2(acc[mt][nt][2] + bx, acc[mt][nt][3] + by);
                *reinterpret_cast<float2*>(base + (size_t)rhi * NHALF + col) = v;
            }
        }
    }
}

// ================= CSR aggregation + BN fused =================
__global__ void __launch_bounds__(256) agg_bn12_kernel(
    const float* __restrict__ hw, const float* __restrict__ selfacc,
    const float* __restrict__ gamma, const float* __restrict__ beta,
    const float* __restrict__ mean, const float* __restrict__ var,
    __nv_bfloat16* __restrict__ hi, __nv_bfloat16* __restrict__ lo)
{
    int v = (blockIdx.x * blockDim.x + threadIdx.x) >> 5;
    if (v >= NN) return;
    int lane = threadIdx.x & 31;
    int beg = g_rowptr[v], end = g_rowptr[v + 1];

    float4 acc = make_float4(0.f, 0.f, 0.f, 0.f);
    int e = beg;
    for (; e + 1 < end; e += 2) {
        int s0 = __ldg(&g_ssrc[e]);
        int s1 = __ldg(&g_ssrc[e + 1]);
        float w0 = __ldg(&g_sw[e]);
        float w1 = __ldg(&g_sw[e + 1]);
        float4 x0 = __ldg(reinterpret_cast<const float4*>(hw + (size_t)s0 * 128) + lane);
        float4 x1 = __ldg(reinterpret_cast<const float4*>(hw + (size_t)s1 * 128) + lane);
        acc.x += w0 * x0.x + w1 * x1.x;
        acc.y += w0 * x0.y + w1 * x1.y;
        acc.z += w0 * x0.z + w1 * x1.z;
        acc.w += w0 * x0.w + w1 * x1.w;
    }
    if (e < end) {
        int s0 = __ldg(&g_ssrc[e]);
        float w0 = __ldg(&g_sw[e]);
        float4 x0 = __ldg(reinterpret_cast<const float4*>(hw + (size_t)s0 * 128) + lane);
        acc.x += w0 * x0.x; acc.y += w0 * x0.y; acc.z += w0 * x0.z; acc.w += w0 * x0.w;
    }

    float4 sf = __ldg(reinterpret_cast<const float4*>(selfacc + (size_t)v * 128) + lane);
    int c = lane * 4;
    float vals[4] = { acc.x + sf.x, acc.y + sf.y, acc.z + sf.z, acc.w + sf.w };
    uint32_t hpack[2], lpack[2];
#pragma unroll
    for (int p = 0; p < 2; p++) {
        __nv_bfloat16 h2[2], l2[2];
#pragma unroll
        for (int j = 0; j < 2; j++) {
            int ch = c + p * 2 + j;
            float t = vals[p * 2 + j];
            t = (t - __ldg(&mean[ch])) * rsqrtf(__ldg(&var[ch]) + EPSBN) * __ldg(&gamma[ch]) + __ldg(&beta[ch]);
            t = fmaxf(t, 0.f);
            __nv_bfloat16 hh = __float2bfloat16(t);
            h2[j] = hh;
            l2[j] = __float2bfloat16(t - __bfloat162float(hh));
        }
        hpack[p] = (uint32_t)*reinterpret_cast<uint16_t*>(&h2[0]) |
                   ((uint32_t)*reinterpret_cast<uint16_t*>(&h2[1]) << 16);
        lpack[p] = (uint32_t)*reinterpret_cast<uint16_t*>(&l2[0]) |
                   ((uint32_t)*reinterpret_cast<uint16_t*>(&l2[1]) << 16);
    }
    *reinterpret_cast<uint2*>(hi + (size_t)v * 128 + c) = make_uint2(hpack[0], hpack[1]);
    *reinterpret_cast<uint2*>(lo + (size_t)v * 128 + c) = make_uint2(lpack[0], lpack[1]);
}

__global__ void __launch_bounds__(256) agg_bn3_kernel(
    const float* __restrict__ hw, const float* __restrict__ selfacc,
    const float* __restrict__ gamma, const float* __restrict__ beta,
    const float* __restrict__ mean, const float* __restrict__ var,
    float* __restrict__ out)
{
    int v = (blockIdx.x * blockDim.x + threadIdx.x) >> 5;
    if (v >= NN) return;
    int lane = threadIdx.x & 31;
    if (lane >= 20) return;
    int beg = g_rowptr[v], end = g_rowptr[v + 1];

    float2 acc = make_float2(0.f, 0.f);
    int e = beg;
    for (; e + 1 < end; e += 2) {
        int s0 = __ldg(&g_ssrc[e]);
        int s1 = __ldg(&g_ssrc[e + 1]);
        float w0 = __ldg(&g_sw[e]);
        float w1 = __ldg(&g_sw[e + 1]);
        float2 x0 = __ldg(reinterpret_cast<const float2*>(hw + (size_t)s0 * NCLS_PAD) + lane);
        float2 x1 = __ldg(reinterpret_cast<const float2*>(hw + (size_t)s1 * NCLS_PAD) + lane);
        acc.x += w0 * x0.x + w1 * x1.x;
        acc.y += w0 * x0.y + w1 * x1.y;
    }
    if (e < end) {
        int s0 = __ldg(&g_ssrc[e]);
        float w0 = __ldg(&g_sw[e]);
        float2 x0 = __ldg(reinterpret_cast<const float2*>(hw + (size_t)s0 * NCLS_PAD) + lane);
        acc.x += w0 * x0.x;
        acc.y += w0 * x0.y;
    }

    float2 sf = __ldg(reinterpret_cast<const float2*>(selfacc + (size_t)v * NCLS_PAD) + lane);
    int c = lane * 2;
    float2 o;
    o.x = (acc.x + sf.x - __ldg(&mean[c]))     * rsqrtf(__ldg(&var[c]) + EPSBN)     * __ldg(&gamma[c])     + __ldg(&beta[c]);
    o.y = (acc.y + sf.y - __ldg(&mean[c + 1])) * rsqrtf(__ldg(&var[c + 1]) + EPSBN) * __ldg(&gamma[c + 1]) + __ldg(&beta[c + 1]);
    *reinterpret_cast<float2*>(out + (size_t)v * NCLS + c) = o;
}

// ================= launch =================
extern "C" void kernel_launch(void* const* d_in, const int* in_sizes, int n_in,
                              void* d_out, int out_size) {
    const float* x   = (const float*)d_in[0];
    const int*   ei  = (const int*)d_in[1];
    const float* ew  = (const float*)d_in[2];
    const int* src = ei;
    const int* dst = ei + EE;

    const float* wg1 = (const float*)d_in[3];
    const float* ws1 = (const float*)d_in[4];
    const float* b1  = (const float*)d_in[5];
    const float* gm1 = (const float*)d_in[6];
    const float* bt1 = (const float*)d_in[7];
    const float* mn1 = (const float*)d_in[8];
    const float* vr1 = (const float*)d_in[9];

    const float* wg2 = (const float*)d_in[10];
    const float* ws2 = (const float*)d_in[11];
    const float* b2  = (const float*)d_in[12];
    const float* gm2 = (const float*)d_in[13];
    const float* bt2 = (const float*)d_in[14];
    const float* mn2 = (const float*)d_in[15];
    const float* vr2 = (const float*)d_in[16];

    const float* wg3 = (const float*)d_in[17];
    const float* ws3 = (const float*)d_in[18];
    const float* b3  = (const float*)d_in[19];
    const float* gm3 = (const float*)d_in[20];
    const float* bt3 = (const float*)d_in[21];
    const float* mn3 = (const float*)d_in[22];
    const float* vr3 = (const float*)d_in[23];

    float* out = (float*)d_out;

    float *p_hw, *p_acc, *p_b3p;
    __nv_bfloat16 *p_xhi, *p_xlo, *p_hhi, *p_hlo;
    __nv_bfloat16 *p_w1hi, *p_w1lo, *p_w2hi, *p_w2lo, *p_w3hi, *p_w3lo;
    cudaGetSymbolAddress((void**)&p_hw,  g_hw);
    cudaGetSymbolAddress((void**)&p_acc, g_acc);
    cudaGetSymbolAddress((void**)&p_b3p, g_b3p);
    cudaGetSymbolAddress((void**)&p_xhi, g_xhi);
    cudaGetSymbolAddress((void**)&p_xlo, g_xlo);
    cudaGetSymbolAddress((void**)&p_hhi, g_hhi);
    cudaGetSymbolAddress((void**)&p_hlo, g_hlo);
    cudaGetSymbolAddress((void**)&p_w1hi, g_w1hi);
    cudaGetSymbolAddress((void**)&p_w1lo, g_w1lo);
    cudaGetSymbolAddress((void**)&p_w2hi, g_w2hi);
    cudaGetSymbolAddress((void**)&p_w2lo, g_w2lo);
    cudaGetSymbolAddress((void**)&p_w3hi, g_w3hi);
    cudaGetSymbolAddress((void**)&p_w3lo, g_w3lo);

    // dynamic smem opt-in for double-buffered GEMM (idempotent host API, no alloc)
    const int GSMEM = 2 * 4 * 128 * 80;  // 81920 bytes
    cudaFuncSetAttribute(gcn_gemm_mma<256, 128>, cudaFuncAttributeMaxDynamicSharedMemorySize, GSMEM);
    cudaFuncSetAttribute(gcn_gemm_mma<128, 128>, cudaFuncAttributeMaxDynamicSharedMemorySize, GSMEM);
    cudaFuncSetAttribute(gcn_gemm_mma<128, 64>,  cudaFuncAttributeMaxDynamicSharedMemorySize, GSMEM);

    const int TPB = 256;
    const int GRID_M = (NN + 127) / 128;           // 391
    const int GRID_W = (NN * 32 + TPB - 1) / TPB;  // warp-per-node grids

    // ---- CSR build + normalization ----
    zero_dc_kernel<<<(NN + TPB - 1) / TPB, TPB>>>();
    count_deg_kernel<<<(EE + TPB - 1) / TPB, TPB>>>(dst, ew, EE);
    dinv_kernel<<<(NN + TPB - 1) / TPB, TPB>>>(NN);
    blocksum_kernel<<<NBLK, SCAN_B>>>();
    scan_bsum_kernel<<<1, SCAN_B>>>();
    scatter_rowptr_kernel<<<NBLK, SCAN_B>>>();
    fill_kernel<<<(EE + TPB - 1) / TPB, TPB>>>(src, dst, ew, EE);

    // ---- prep: transposed bf16 hi/lo weights, x split ----
    prep_w_kernel<<<(2 * 128 * 256 + TPB - 1) / TPB, TPB>>>(wg1, ws1, 256, 128, 128, p_w1hi, p_w1lo);
    prep_w_kernel<<<(2 * 128 * 128 + TPB - 1) / TPB, TPB>>>(wg2, ws2, 128, 128, 128, p_w2hi, p_w2lo);
    prep_w_kernel<<<(2 * 64 * 128 + TPB - 1) / TPB, TPB>>>(wg3, ws3, 128, 40, 64, p_w3hi, p_w3lo);
    prep_b3_kernel<<<1, 64>>>(b3);
    split_kernel<<<(NN * F_IN + TPB - 1) / TPB, TPB>>>(x, p_xhi, p_xlo, NN * F_IN);

    // ---- layer 1 ----
    gcn_gemm_mma<256, 128><<<dim3(GRID_M, 2), 256, GSMEM>>>(p_xhi, p_xlo, p_w1hi, p_w1lo, b1, p_hw, p_acc, NN);
    agg_bn12_kernel<<<GRID_W, TPB>>>(p_hw, p_acc, gm1, bt1, mn1, vr1, p_hhi, p_hlo);

    // ---- layer 2 ----
    gcn_gemm_mma<128, 128><<<dim3(GRID_M, 2), 256, GSMEM>>>(p_hhi, p_hlo, p_w2hi, p_w2lo, b2, p_hw, p_acc, NN);
    agg_bn12_kernel<<<GRID_W, TPB>>>(p_hw, p_acc, gm2, bt2, mn2, vr2, p_hhi, p_hlo);

    // ---- layer 3 ----
    gcn_gemm_mma<128, 64><<<dim3(GRID_M, 1), 256, GSMEM>>>(p_hhi, p_hlo, p_w3hi, p_w3lo, p_b3p, p_hw, p_acc, NN);
    agg_bn3_kernel<<<GRID_W, TPB>>>(p_hw, p_acc, gm3, bt3, mn3, vr3, out);
}